// round 13
// baseline (speedup 1.0000x reference)
#include <cuda_runtime.h>
#include <math.h>

#define BB 32
#define TT 48
#define DIN 256
#define HH 512
#define MM 256
#define WWID 64
#define RR 4
#define IFACE 471
#define NIF 983
#define EPSV 1e-6f

#define RK_OFF 0
#define RS_OFF 256
#define WK_OFF 260
#define WS_OFF 324
#define ER_OFF 325
#define WV_OFF 389
#define FG_OFF 453
#define AG_OFF 457
#define WG_OFF 458
#define RM_OFF 459

// -------- state --------
__device__ float g_h0[2][BB*HH];
__device__ float g_c0[BB*HH];
__device__ float g_h1[2][BB*HH];
__device__ float g_c1[BB*HH];
__device__ float g_mem[BB*MM*WWID];
__device__ float g_link[2][(size_t)BB*MM*MM];
__device__ float g_prec[2][BB*MM];
__device__ float g_rw[2][BB*RR*MM];
__device__ float g_ww[BB*MM];
__device__ float g_usage[BB*MM];
__device__ float g_memnorm[BB*MM];
__device__ float g_v[BB*IFACE];
__device__ float g_cwr[BB*RR*MM];
__device__ float g_wwsum[BB];
__device__ float g_outbuf[2][BB*HH];     // parity double-buffered
__device__ float g_rvbuf[BB*RR*WWID];
__device__ float g_out2[BB*HH];
__device__ float g_xg[(size_t)BB*TT*4*HH];

__device__ __forceinline__ float sigm(float x){ return 1.f/(1.f+expf(-x)); }
__device__ __forceinline__ float softplusf(float x){ return fmaxf(x,0.f) + log1pf(expf(-fabsf(x))); }
__device__ __forceinline__ float redw(float s){
  #pragma unroll
  for (int o=16;o;o>>=1) s += __shfl_xor_sync(0xffffffffu, s, o);
  return s;
}

// ---------------- init ----------------
__global__ void k_init(){
  size_t i = (size_t)blockIdx.x*blockDim.x + threadIdx.x;
  if (i < (size_t)BB*MM*MM){ g_link[0][i]=0.f; g_link[1][i]=0.f; }
  if (i < BB*MM*WWID) g_mem[i] = 0.f;
  if (i < BB*RR*MM){ g_rw[0][i]=0.f; g_rw[1][i]=0.f; }
  if (i < BB*HH){ g_h0[0][i]=0.f; g_h0[1][i]=0.f; g_c0[i]=0.f;
                  g_h1[0][i]=0.f; g_h1[1][i]=0.f; g_c1[i]=0.f; }
  if (i < BB*MM){ g_prec[0][i]=0.f; g_prec[1][i]=0.f; g_ww[i]=0.f; g_usage[i]=0.f; g_memnorm[i]=0.f; }
}

// ====== warp-GEMV: 4 batches x 4 rows per warp, scalar accumulators ======
#define FMA4S(A,V,W) { A += (V).x*(W).x; A += (V).y*(W).y; A += (V).z*(W).z; A += (V).w*(W).w; }

__device__ __forceinline__ void wgemv16(
    const float* __restrict__ X, int xld, int b0,
    const float* __restrict__ r0, const float* __restrict__ r1,
    const float* __restrict__ r2, const float* __restrict__ r3,
    int K, float acc[16])
{
  const int lane = threadIdx.x & 31;
  const float4* x0 = (const float4*)(X + (size_t)(b0+0)*xld);
  const float4* x1 = (const float4*)(X + (size_t)(b0+1)*xld);
  const float4* x2 = (const float4*)(X + (size_t)(b0+2)*xld);
  const float4* x3 = (const float4*)(X + (size_t)(b0+3)*xld);
  const float4* w0 = (const float4*)r0;
  const float4* w1 = (const float4*)r1;
  const float4* w2 = (const float4*)r2;
  const float4* w3 = (const float4*)r3;
  const int K4 = K >> 2;
  for (int k = lane; k < K4; k += 32){
    float4 a = x0[k], b = x1[k], c = x2[k], d = x3[k];
    float4 wv;
    wv = w0[k]; FMA4S(acc[0],a,wv)  FMA4S(acc[4],b,wv)  FMA4S(acc[8],c,wv)  FMA4S(acc[12],d,wv)
    wv = w1[k]; FMA4S(acc[1],a,wv)  FMA4S(acc[5],b,wv)  FMA4S(acc[9],c,wv)  FMA4S(acc[13],d,wv)
    wv = w2[k]; FMA4S(acc[2],a,wv)  FMA4S(acc[6],b,wv)  FMA4S(acc[10],c,wv) FMA4S(acc[14],d,wv)
    wv = w3[k]; FMA4S(acc[3],a,wv)  FMA4S(acc[7],b,wv)  FMA4S(acc[11],c,wv) FMA4S(acc[15],d,wv)
  }
}
#define ZACC16 float acc[16]; _Pragma("unroll") for (int i_=0;i_<16;i_++) acc[i_]=0.f;
#define RED16  float r[16];   _Pragma("unroll") for (int i_=0;i_<16;i_++) r[i_]=redw(acc[i_]);

// ---------------- pregemm (one-time) ----------------
__global__ void __launch_bounds__(256) k_pregemm(const float* __restrict__ x,
    const float* __restrict__ Wi, const float* __restrict__ bi, const float* __restrict__ bh)
{
  int gw = blockIdx.x*8 + (threadIdx.x>>5);
  int ng = gw >> 9, u = gw & 511;
  int n0 = ng*4;
  ZACC16
  wgemv16(x, DIN, n0,
          Wi + (size_t)(0*HH+u)*DIN, Wi + (size_t)(1*HH+u)*DIN,
          Wi + (size_t)(2*HH+u)*DIN, Wi + (size_t)(3*HH+u)*DIN, DIN, acc);
  RED16
  int lane = threadIdx.x & 31;
  if (lane < 4){
    int n = n0 + lane;
    #pragma unroll
    for (int g=0; g<4; g++)
      g_xg[(size_t)n*(4*HH) + g*HH + u] = r[lane*4+g] + bi[g*HH+u] + bh[g*HH+u];
  }
}

// ---------------- role bodies ----------------
__device__ void lstm0_body(const float* __restrict__ Wh, int t, int rp, int vbid)
{
  int gw = vbid*8 + (threadIdx.x>>5);
  int bg = gw >> 9, u = gw & 511;
  int b0 = bg*4;
  ZACC16
  wgemv16(g_h0[rp], HH, b0,
          Wh + (size_t)(0*HH+u)*HH, Wh + (size_t)(1*HH+u)*HH,
          Wh + (size_t)(2*HH+u)*HH, Wh + (size_t)(3*HH+u)*HH, HH, acc);
  RED16
  int lane = threadIdx.x & 31;
  if (lane < 4){
    int b = b0 + lane;
    const float* xg = g_xg + ((size_t)b*TT + t)*(4*HH);
    float gi = r[lane*4+0] + xg[0*HH+u];
    float gf = r[lane*4+1] + xg[1*HH+u];
    float gg = r[lane*4+2] + xg[2*HH+u];
    float go = r[lane*4+3] + xg[3*HH+u];
    int ci = b*HH + u;
    float c2 = sigm(gf)*g_c0[ci] + sigm(gi)*tanhf(gg);
    g_c0[ci] = c2;
    g_h0[1-rp][ci] = sigm(go)*tanhf(c2);
  }
}

__device__ void lstm1_body(const float* __restrict__ Wi, const float* __restrict__ bi,
    const float* __restrict__ Wh, const float* __restrict__ bh, int rp, int vbid)
{
  int gw = vbid*8 + (threadIdx.x>>5);
  int bg = gw >> 9, u = gw & 511;
  int b0 = bg*4;
  ZACC16
  wgemv16(g_h0[1-rp], HH, b0,
          Wi + (size_t)(0*HH+u)*HH, Wi + (size_t)(1*HH+u)*HH,
          Wi + (size_t)(2*HH+u)*HH, Wi + (size_t)(3*HH+u)*HH, HH, acc);
  wgemv16(g_h1[rp], HH, b0,
          Wh + (size_t)(0*HH+u)*HH, Wh + (size_t)(1*HH+u)*HH,
          Wh + (size_t)(2*HH+u)*HH, Wh + (size_t)(3*HH+u)*HH, HH, acc);
  RED16
  int lane = threadIdx.x & 31;
  if (lane < 4){
    int b = b0 + lane;
    float gi = r[lane*4+0] + bi[0*HH+u] + bh[0*HH+u];
    float gf = r[lane*4+1] + bi[1*HH+u] + bh[1*HH+u];
    float gg = r[lane*4+2] + bi[2*HH+u] + bh[2*HH+u];
    float go = r[lane*4+3] + bi[3*HH+u] + bh[3*HH+u];
    int ci = b*HH + u;
    float c2 = sigm(gf)*g_c1[ci] + sigm(gi)*tanhf(gg);
    g_c1[ci] = c2;
    g_h1[1-rp][ci] = sigm(go)*tanhf(c2);
  }
}

__device__ void iface_body(const float* __restrict__ Wif, const float* __restrict__ bif,
    const float* __restrict__ Wmo, const float* __restrict__ bmo, int rp, int vbid)
{
  int gw = vbid*8 + (threadIdx.x>>5);          // 1968 warps = 8 bg x 246 rg
  int bg = gw / 246, rg = gw % 246;
  int b0 = bg*4, rb = rg*4;
  int rr4[4]; const float* rp_[4];
  #pragma unroll
  for (int j=0;j<4;j++){
    int rrow = rb + j; if (rrow > NIF-1) rrow = NIF-1;
    rr4[j] = rrow;
    rp_[j] = (rrow < IFACE) ? (Wif + (size_t)rrow*HH) : (Wmo + (size_t)(rrow-IFACE)*HH);
  }
  ZACC16
  wgemv16(g_h1[1-rp], HH, b0, rp_[0], rp_[1], rp_[2], rp_[3], HH, acc);
  RED16
  int lane = threadIdx.x & 31;
  if (lane < 4){
    int b = b0 + lane;
    #pragma unroll
    for (int j=0;j<4;j++){
      int row = rr4[j];
      float val = r[lane*4+j] + ((row < IFACE) ? bif[row] : bmo[row-IFACE]);
      if (row < IFACE) g_v[b*IFACE + row] = val;
      else             g_outbuf[rp][b*HH + (row-IFACE)] = val;
    }
  }
}

// rv(t-1): reads rw written by rw2(t-1) = g_rw[1-rp_prev].
__device__ void rv_body(int rp_prev, int br)
{
  __shared__ float part[4][64];
  int tt = threadIdx.x, w = tt & 63, mq = tt >> 6;
  int b = br >> 2;
  const float* rwn = g_rw[1-rp_prev] + br*MM;
  const float* mb = g_mem + (size_t)b*MM*WWID;
  float acc = 0.f;
  #pragma unroll 8
  for (int m2 = mq*64; m2 < mq*64+64; m2++) acc += rwn[m2]*mb[(size_t)m2*WWID + w];
  part[mq][w] = acc;
  __syncthreads();
  if (mq == 0) g_rvbuf[br*WWID + w] = part[0][w]+part[1][w]+part[2][w]+part[3][w];
}

__device__ void wrv_body(const float* __restrict__ Wrv, const float* __restrict__ brv,
    int rp_prev, int vbid)
{
  int gw = vbid*8 + (threadIdx.x>>5);   // 1024 warps
  int bg = gw >> 7, rg = gw & 127;
  int b0 = bg*4, rb = rg*4;
  ZACC16
  wgemv16(g_rvbuf, RR*WWID, b0,
          Wrv + (size_t)(rb+0)*(RR*WWID), Wrv + (size_t)(rb+1)*(RR*WWID),
          Wrv + (size_t)(rb+2)*(RR*WWID), Wrv + (size_t)(rb+3)*(RR*WWID),
          RR*WWID, acc);
  RED16
  int lane = threadIdx.x & 31;
  if (lane < 4){
    int b = b0 + lane;
    #pragma unroll
    for (int j=0;j<4;j++){
      int row = rb + j;
      g_out2[b*HH + row] = r[lane*4+j] + brv[row] + g_outbuf[rp_prev][b*HH + row];
    }
  }
}

__device__ void wout_body(const float* __restrict__ Wout, const float* __restrict__ bout,
    float* __restrict__ y, int tprev, int vbid)
{
  int gw = vbid*8 + (threadIdx.x>>5);   // 512 warps
  int bg = gw >> 6, rg = gw & 63;
  int b0 = bg*4, rb = rg*4;
  ZACC16
  wgemv16(g_out2, HH, b0,
          Wout + (size_t)(rb+0)*HH, Wout + (size_t)(rb+1)*HH,
          Wout + (size_t)(rb+2)*HH, Wout + (size_t)(rb+3)*HH, HH, acc);
  RED16
  int lane = threadIdx.x & 31;
  if (lane < 4){
    int b = b0 + lane;
    #pragma unroll
    for (int j=0;j<4;j++){
      int row = rb + j;
      y[((size_t)b*TT + tprev)*DIN + row] = r[lane*4+j] + bout[row];
    }
  }
}

// ---------------- block reductions ----------------
__device__ __forceinline__ float blkmax(float v, volatile float* s8){
  #pragma unroll
  for (int o=16;o;o>>=1) v = fmaxf(v, __shfl_xor_sync(0xffffffffu, v, o));
  if ((threadIdx.x & 31)==0) s8[threadIdx.x>>5] = v;
  __syncthreads();
  float rr = s8[0];
  #pragma unroll
  for (int i=1;i<8;i++) rr = fmaxf(rr, s8[i]);
  __syncthreads();
  return rr;
}
__device__ __forceinline__ float blksum(float v, volatile float* s8){
  #pragma unroll
  for (int o=16;o;o>>=1) v += __shfl_xor_sync(0xffffffffu, v, o);
  if ((threadIdx.x & 31)==0) s8[threadIdx.x>>5] = v;
  __syncthreads();
  float rr = 0.f;
  #pragma unroll
  for (int i=0;i<8;i++) rr += s8[i];
  __syncthreads();
  return rr;
}

// ---- fused memory module ----
__device__ void mem1_body(int rp, int b)
{
  __shared__ float swk[WWID], ser[WWID], swv[WWID], srk[RR*WWID];
  __shared__ float s8[8];
  __shared__ float skey[MM]; __shared__ int sidx[MM];
  __shared__ float sprod[MM], salloc[MM];
  __shared__ float sc[12];
  int m = threadIdx.x;
  const float* vb = g_v + b*IFACE;
  if (m < WWID){ swk[m]=tanhf(vb[WK_OFF+m]); ser[m]=sigm(vb[ER_OFF+m]); swv[m]=tanhf(vb[WV_OFF+m]); }
  srk[m] = tanhf(vb[RK_OFF + m]);
  __syncthreads();
  if (m == 0){
    float s=0.f; for (int w=0;w<WWID;w++) s += swk[w]*swk[w];
    sc[0]=sqrtf(s)+EPSV; sc[1]=softplusf(vb[WS_OFF]);
    sc[10]=sigm(vb[AG_OFF]); sc[11]=sigm(vb[WG_OFF]);
  }
  if (m >= 32 && m < 36){
    int rh = m-32; float s=0.f;
    for (int w=0;w<WWID;w++) s += srk[rh*WWID+w]*srk[rh*WWID+w];
    sc[2+rh]=sqrtf(s)+EPSV; sc[6+rh]=softplusf(vb[RS_OFF+rh]);
  }
  __syncthreads();
  float4 mrow[16];
  float4* mr = (float4*)(g_mem + (size_t)(b*MM+m)*WWID);
  #pragma unroll
  for (int i=0;i<16;i++) mrow[i] = mr[i];
  const float* rwp = g_rw[rp] + b*RR*MM;
  float psi = 1.f;
  #pragma unroll
  for (int rh=0;rh<RR;rh++) psi *= (1.f - sigm(vb[FG_OFF+rh])*rwp[rh*MM+m]);
  float us = g_usage[b*MM+m], wwp = g_ww[b*MM+m];
  us = (us + (1.f-us)*wwp)*psi;
  float dot = 0.f;
  #pragma unroll
  for (int i=0;i<16;i++)
    dot += mrow[i].x*swk[4*i] + mrow[i].y*swk[4*i+1] + mrow[i].z*swk[4*i+2] + mrow[i].w*swk[4*i+3];
  float score = dot/((g_memnorm[b*MM+m]+EPSV)*sc[0]) * sc[1];
  float mx = blkmax(score, s8);
  float e  = expf(score - mx);
  float sm = blksum(e, s8);
  float cww = e/sm;
  float uval = EPSV + (1.f-EPSV)*us;
  skey[m]=uval; sidx[m]=m; __syncthreads();
  for (int k=2;k<=MM;k<<=1){
    for (int j=k>>1;j>0;j>>=1){
      int p = m ^ j;
      if (p > m){
        float ka=skey[m], kb=skey[p]; int ia=sidx[m], ib=sidx[p];
        bool agtb = (ka>kb)||(ka==kb&&ia>ib);
        bool up = ((m & k)==0);
        if (up==agtb){ skey[m]=kb;skey[p]=ka;sidx[m]=ib;sidx[p]=ia; }
      }
      __syncthreads();
    }
  }
  sprod[m]=skey[m]; __syncthreads();
  for (int off=1;off<MM;off<<=1){
    float tv = (m>=off)? sprod[m-off] : 1.f;
    __syncthreads();
    sprod[m] *= tv;
    __syncthreads();
  }
  salloc[sidx[m]] = (1.f - skey[m]) * ((m==0)?1.f:sprod[m-1]);
  __syncthreads();
  float wwv = sc[11]*(sc[10]*salloc[m] + (1.f-sc[10])*cww);
  g_ww[b*MM+m] = wwv;
  g_usage[b*MM+m] = us;
  float wsum = blksum(wwv, s8);
  if (m==0) g_wwsum[b] = wsum;
  float nrm=0.f, d0=0.f, d1=0.f, d2=0.f, d3=0.f;
  #pragma unroll
  for (int i=0;i<16;i++){
    float4 mv = mrow[i];
    int w0 = 4*i;
    mv.x = mv.x*(1.f - wwv*ser[w0  ]) + wwv*swv[w0  ];
    mv.y = mv.y*(1.f - wwv*ser[w0+1]) + wwv*swv[w0+1];
    mv.z = mv.z*(1.f - wwv*ser[w0+2]) + wwv*swv[w0+2];
    mv.w = mv.w*(1.f - wwv*ser[w0+3]) + wwv*swv[w0+3];
    nrm += mv.x*mv.x + mv.y*mv.y + mv.z*mv.z + mv.w*mv.w;
    d0 += mv.x*srk[0*WWID+w0] + mv.y*srk[0*WWID+w0+1] + mv.z*srk[0*WWID+w0+2] + mv.w*srk[0*WWID+w0+3];
    d1 += mv.x*srk[1*WWID+w0] + mv.y*srk[1*WWID+w0+1] + mv.z*srk[1*WWID+w0+2] + mv.w*srk[1*WWID+w0+3];
    d2 += mv.x*srk[2*WWID+w0] + mv.y*srk[2*WWID+w0+1] + mv.z*srk[2*WWID+w0+2] + mv.w*srk[2*WWID+w0+3];
    d3 += mv.x*srk[3*WWID+w0] + mv.y*srk[3*WWID+w0+1] + mv.z*srk[3*WWID+w0+2] + mv.w*srk[3*WWID+w0+3];
    mr[i] = mv;
  }
  float mn = sqrtf(nrm);
  g_memnorm[b*MM+m] = mn;
  float mne = mn + EPSV;
  float dd[4] = {d0,d1,d2,d3};
  #pragma unroll
  for (int rh=0;rh<RR;rh++){
    float sr = dd[rh]/(mne*sc[2+rh]) * sc[6+rh];
    float mx2 = blkmax(sr, s8);
    float e2 = expf(sr - mx2);
    float s2 = blksum(e2, s8);
    g_cwr[(b*RR+rh)*MM+m] = e2/s2;
  }
}

// ---- fused link update + fwd/bwd + read weights + prec ----
__device__ void rw2_body(int rp, int blk)
{
  __shared__ float srw[RR][MM];
  __shared__ float sww[MM], sprec[MM];
  __shared__ float ft[64][65];
  __shared__ float bt[64][64];
  __shared__ float fpart[4][64][RR];
  __shared__ float bpart[4][64][RR];
  int b = blk >> 2, ig = blk & 3;
  int t = threadIdx.x;
  int I0 = ig*64;
  const float* rwp = g_rw[rp] + b*RR*MM;
  #pragma unroll
  for (int rh=0;rh<RR;rh++) srw[rh][t] = rwp[rh*MM+t];
  sww[t] = g_ww[b*MM+t];
  sprec[t] = g_prec[rp][b*MM+t];
  __syncthreads();

  const float* lold = g_link[rp]   + (size_t)b*MM*MM;
  float*       lnew = g_link[1-rp] + (size_t)b*MM*MM;
  int il2 = t & 63, q2 = t >> 6;
  float fa[RR] = {0.f,0.f,0.f,0.f};
  float ba[RR] = {0.f,0.f,0.f,0.f};

  for (int jq = 0; jq < 4; jq++){
    int J0 = jq*64;
    #pragma unroll
    for (int p = 0; p < 16; p++){
      int e = p*256 + t;
      int il = e >> 6, jl = e & 63;
      int i = I0 + il, j = J0 + jl;
      float lo = lold[((size_t)i<<8) + j];
      float ln = (i==j) ? 0.f : (1.f - sww[i] - sww[j])*lo + sww[i]*sprec[j];
      lnew[((size_t)i<<8) + j] = ln;
      ft[il][jl] = ln;
    }
    #pragma unroll
    for (int p = 0; p < 16; p++){
      int e = p*256 + t;
      int jl = e >> 6, il = e & 63;
      int i = I0 + il, j = J0 + jl;
      float lo = lold[((size_t)j<<8) + i];
      float ln = (i==j) ? 0.f : (1.f - sww[j] - sww[i])*lo + sww[j]*sprec[i];
      bt[jl][il] = ln;
    }
    __syncthreads();
    #pragma unroll
    for (int jj = 0; jj < 16; jj++){
      int jl = q2*16 + jj;
      float fv = ft[il2][jl];
      float bv = bt[jl][il2];
      float rw0 = srw[0][J0+jl], rw1 = srw[1][J0+jl], rw2v = srw[2][J0+jl], rw3 = srw[3][J0+jl];
      fa[0] += fv*rw0; fa[1] += fv*rw1; fa[2] += fv*rw2v; fa[3] += fv*rw3;
      ba[0] += bv*rw0; ba[1] += bv*rw1; ba[2] += bv*rw2v; ba[3] += bv*rw3;
    }
    __syncthreads();
  }
  #pragma unroll
  for (int rh=0;rh<RR;rh++){ fpart[q2][il2][rh]=fa[rh]; bpart[q2][il2][rh]=ba[rh]; }
  __syncthreads();
  if (t < 64){
    int i = I0 + t;
    const float* vb = g_v + b*IFACE;
    float* rwn = g_rw[1-rp] + b*RR*MM;
    #pragma unroll
    for (int rh=0;rh<RR;rh++){
      float fr = fpart[0][t][rh]+fpart[1][t][rh]+fpart[2][t][rh]+fpart[3][t][rh];
      float wr = bpart[0][t][rh]+bpart[1][t][rh]+bpart[2][t][rh]+bpart[3][t][rh];
      float x0 = vb[RM_OFF+rh*3], x1 = vb[RM_OFF+rh*3+1], x2 = vb[RM_OFF+rh*3+2];
      float mx = fmaxf(x0, fmaxf(x1, x2));
      float e0 = expf(x0-mx), e1 = expf(x1-mx), e2 = expf(x2-mx);
      float inv = 1.f/(e0+e1+e2);
      rwn[rh*MM+i] = (e0*wr + e1*fr + e2*g_cwr[(b*RR+rh)*MM+i])*inv;
    }
    g_prec[1-rp][b*MM+i] = (1.f - g_wwsum[b])*sprec[i] + sww[i];
  }
}

// ---------------- dispatcher kernels ----------
// kA(t): lstm1(t) [0,512) + lstm0(t+1) [512,1024) + rw2(t-1) [1024,1152) + wout(t-2) [1152,1216)
//   rw2(t-1) reads g_v(t-1) (iface t-1) — overwritten only by kB(t) after kA(t);
//   reads g_ww/g_cwr/g_wwsum from mem1(t-1) (kC(t-1)); parity rw/link/prec ping-pong.
//   wout(t-2) reads g_out2 (wrv(t-2), kC(t-1)) — overwritten only by kC(t).
__global__ void __launch_bounds__(256) kA(const float* __restrict__ Wi, const float* __restrict__ bi,
    const float* __restrict__ Wh, const float* __restrict__ bh,
    const float* __restrict__ Wh0,
    const float* __restrict__ Wout, const float* __restrict__ bout, float* __restrict__ y,
    int rp, int tnext, int en_l0, int en_rw2, int en_wo)
{
  if (blockIdx.x < 512)        lstm1_body(Wi, bi, Wh, bh, rp, blockIdx.x);
  else if (blockIdx.x < 1024){ if (en_l0)  lstm0_body(Wh0, tnext, 1-rp, blockIdx.x - 512); }
  else if (blockIdx.x < 1152){ if (en_rw2) rw2_body(1-rp, blockIdx.x - 1024); }
  else if (en_wo)              wout_body(Wout, bout, y, tnext-3, blockIdx.x - 1152);
}
// kB(t): iface(t) [0,246) + rv(t-1) [246,374)
__global__ void __launch_bounds__(256) kB(const float* __restrict__ Wif, const float* __restrict__ bif,
    const float* __restrict__ Wmo, const float* __restrict__ bmo, int rp, int en_rv)
{
  if (blockIdx.x < 246) iface_body(Wif, bif, Wmo, bmo, rp, blockIdx.x);
  else if (en_rv)       rv_body(1-rp, blockIdx.x - 246);
}
// kC(t): mem1(t) [0,32) + wrv(t-1) [32,160)
__global__ void __launch_bounds__(256) kC(const float* __restrict__ Wrv, const float* __restrict__ brv,
    int rp, int en_wrv)
{
  if (blockIdx.x < 32) mem1_body(rp, blockIdx.x);
  else if (en_wrv)     wrv_body(Wrv, brv, 1-rp, blockIdx.x - 32);
}

// prologue / epilogue standalone kernels
__global__ void __launch_bounds__(256) k_lstm0s(const float* __restrict__ Wh, int t, int rp)
{ lstm0_body(Wh, t, rp, blockIdx.x); }
__global__ void __launch_bounds__(256) k_rw2s(int rp)
{ rw2_body(rp, blockIdx.x); }
__global__ void __launch_bounds__(256) k_rvs(int rp_prev)
{ rv_body(rp_prev, blockIdx.x); }
__global__ void __launch_bounds__(256) k_wrvs(const float* __restrict__ Wrv, const float* __restrict__ brv, int rp_prev)
{ wrv_body(Wrv, brv, rp_prev, blockIdx.x); }
__global__ void __launch_bounds__(256) k_wouts(const float* __restrict__ Wout, const float* __restrict__ bout,
    float* __restrict__ y, int tprev)
{ wout_body(Wout, bout, y, tprev, blockIdx.x); }

// ---------------- host: single-stream, 3 launches per step ----------------
extern "C" void kernel_launch(void* const* d_in, const int* in_sizes, int n_in,
                              void* d_out, int out_size)
{
  const float* x     = (const float*)d_in[0];
  const float* Wih0  = (const float*)d_in[1];
  const float* bih0  = (const float*)d_in[2];
  const float* Whh0  = (const float*)d_in[3];
  const float* bhh0  = (const float*)d_in[4];
  const float* Wih1  = (const float*)d_in[5];
  const float* bih1  = (const float*)d_in[6];
  const float* Whh1  = (const float*)d_in[7];
  const float* bhh1  = (const float*)d_in[8];
  const float* Wif   = (const float*)d_in[9];
  const float* bif   = (const float*)d_in[10];
  const float* Wmo   = (const float*)d_in[11];
  const float* bmo   = (const float*)d_in[12];
  const float* Wrv   = (const float*)d_in[13];
  const float* brv   = (const float*)d_in[14];
  const float* Wout  = (const float*)d_in[15];
  const float* bout  = (const float*)d_in[16];
  float* y = (float*)d_out;

  k_init<<<(BB*MM*MM)/256, 256>>>();
  k_pregemm<<<(BB*TT/4)*(HH/8), 256>>>(x, Wih0, bih0, bhh0);
  k_lstm0s<<<512, 256>>>(Whh0, 0, 0);     // prologue: lstm0(0)

  for (int t = 0; t < TT; t++){
    int rp = t & 1;
    // kA: lstm1(t) + lstm0(t+1) + rw2(t-1) + wout(t-2)
    kA<<<1216, 256>>>(Wih1, bih1, Whh1, bhh1, Whh0, Wout, bout, y,
                      rp, t+1, t < TT-1, t > 0, t > 1);
    // kB: iface(t) + rv(t-1)
    kB<<<374, 256>>>(Wif, bif, Wmo, bmo, rp, t > 0);
    // kC: mem1(t) + wrv(t-1)
    kC<<<160, 256>>>(Wrv, brv, rp, t > 0);
  }
  // epilogue: wout(TT-2) [g_out2 from wrv(TT-2) in kC(TT-1)], then the full
  // tail of t = TT-1 (rp = 1): rw2(47) -> rv(47) -> wrv(47) -> wout(47)
  k_wouts<<<64, 256>>>(Wout, bout, y, TT-2);
  k_rw2s<<<128, 256>>>(1);
  k_rvs<<<128, 256>>>(1);
  k_wrvs<<<128, 256>>>(Wrv, brv, 1);
  k_wouts<<<64, 256>>>(Wout, bout, y, TT-1);
}

// round 14
// speedup vs baseline: 1.2133x; 1.2133x over previous
#include <cuda_runtime.h>
#include <math.h>

#define BB 32
#define TT 48
#define DIN 256
#define HH 512
#define MM 256
#define WWID 64
#define RR 4
#define IFACE 471
#define NIF 983
#define EPSV 1e-6f

#define RK_OFF 0
#define RS_OFF 256
#define WK_OFF 260
#define WS_OFF 324
#define ER_OFF 325
#define WV_OFF 389
#define FG_OFF 453
#define AG_OFF 457
#define WG_OFF 458
#define RM_OFF 459

// -------- state --------
__device__ float g_h0[2][BB*HH];
__device__ float g_c0[BB*HH];
__device__ float g_h1[2][BB*HH];
__device__ float g_c1[BB*HH];
__device__ float g_mem[BB*MM*WWID];
__device__ float g_link[2][(size_t)BB*MM*MM];
__device__ float g_prec[2][BB*MM];
__device__ float g_rw[2][BB*RR*MM];
__device__ float g_ww[BB*MM];
__device__ float g_usage[BB*MM];
__device__ float g_memnorm[BB*MM];
__device__ float g_v[BB*IFACE];
__device__ float g_cwr[BB*RR*MM];
__device__ float g_wwsum[BB];
__device__ float g_outbuf[2][BB*HH];     // parity double-buffered
__device__ float g_rvbuf[BB*RR*WWID];
__device__ float g_out2[BB*HH];
__device__ float g_xg[(size_t)BB*TT*4*HH];

__device__ __forceinline__ float sigm(float x){ return 1.f/(1.f+expf(-x)); }
__device__ __forceinline__ float softplusf(float x){ return fmaxf(x,0.f) + log1pf(expf(-fabsf(x))); }
__device__ __forceinline__ float redw(float s){
  #pragma unroll
  for (int o=16;o;o>>=1) s += __shfl_xor_sync(0xffffffffu, s, o);
  return s;
}

// ---------------- init ----------------
__global__ void k_init(){
  size_t i = (size_t)blockIdx.x*blockDim.x + threadIdx.x;
  if (i < (size_t)BB*MM*MM){ g_link[0][i]=0.f; g_link[1][i]=0.f; }
  if (i < BB*MM*WWID) g_mem[i] = 0.f;
  if (i < BB*RR*MM){ g_rw[0][i]=0.f; g_rw[1][i]=0.f; }
  if (i < BB*HH){ g_h0[0][i]=0.f; g_h0[1][i]=0.f; g_c0[i]=0.f;
                  g_h1[0][i]=0.f; g_h1[1][i]=0.f; g_c1[i]=0.f; }
  if (i < BB*MM){ g_prec[0][i]=0.f; g_prec[1][i]=0.f; g_ww[i]=0.f; g_usage[i]=0.f; g_memnorm[i]=0.f; }
}

// ====== warp-GEMV: 4 batches x 4 rows per warp, scalar accumulators ======
// NEW (R14): callers map the 8 warps of a block to the 8 batch-groups of the
// SAME row-tile, so all warps of a block issue identical weight addresses and
// share them through L1 (8x less L2 weight traffic).
#define FMA4S(A,V,W) { A += (V).x*(W).x; A += (V).y*(W).y; A += (V).z*(W).z; A += (V).w*(W).w; }

__device__ __forceinline__ void wgemv16(
    const float* __restrict__ X, int xld, int b0,
    const float* __restrict__ r0, const float* __restrict__ r1,
    const float* __restrict__ r2, const float* __restrict__ r3,
    int K, float acc[16])
{
  const int lane = threadIdx.x & 31;
  const float4* x0 = (const float4*)(X + (size_t)(b0+0)*xld);
  const float4* x1 = (const float4*)(X + (size_t)(b0+1)*xld);
  const float4* x2 = (const float4*)(X + (size_t)(b0+2)*xld);
  const float4* x3 = (const float4*)(X + (size_t)(b0+3)*xld);
  const float4* w0 = (const float4*)r0;
  const float4* w1 = (const float4*)r1;
  const float4* w2 = (const float4*)r2;
  const float4* w3 = (const float4*)r3;
  const int K4 = K >> 2;
  for (int k = lane; k < K4; k += 32){
    float4 a = x0[k], b = x1[k], c = x2[k], d = x3[k];
    float4 wv;
    wv = w0[k]; FMA4S(acc[0],a,wv)  FMA4S(acc[4],b,wv)  FMA4S(acc[8],c,wv)  FMA4S(acc[12],d,wv)
    wv = w1[k]; FMA4S(acc[1],a,wv)  FMA4S(acc[5],b,wv)  FMA4S(acc[9],c,wv)  FMA4S(acc[13],d,wv)
    wv = w2[k]; FMA4S(acc[2],a,wv)  FMA4S(acc[6],b,wv)  FMA4S(acc[10],c,wv) FMA4S(acc[14],d,wv)
    wv = w3[k]; FMA4S(acc[3],a,wv)  FMA4S(acc[7],b,wv)  FMA4S(acc[11],c,wv) FMA4S(acc[15],d,wv)
  }
}
#define ZACC16 float acc[16]; _Pragma("unroll") for (int i_=0;i_<16;i_++) acc[i_]=0.f;
#define RED16  float r[16];   _Pragma("unroll") for (int i_=0;i_<16;i_++) r[i_]=redw(acc[i_]);

// ---------------- pregemm (one-time) ----------------
__global__ void __launch_bounds__(256) k_pregemm(const float* __restrict__ x,
    const float* __restrict__ Wi, const float* __restrict__ bi, const float* __restrict__ bh)
{
  int gw = blockIdx.x*8 + (threadIdx.x>>5);
  int ng = gw >> 9, u = gw & 511;
  int n0 = ng*4;
  ZACC16
  wgemv16(x, DIN, n0,
          Wi + (size_t)(0*HH+u)*DIN, Wi + (size_t)(1*HH+u)*DIN,
          Wi + (size_t)(2*HH+u)*DIN, Wi + (size_t)(3*HH+u)*DIN, DIN, acc);
  RED16
  int lane = threadIdx.x & 31;
  if (lane < 4){
    int n = n0 + lane;
    #pragma unroll
    for (int g=0; g<4; g++)
      g_xg[(size_t)n*(4*HH) + g*HH + u] = r[lane*4+g] + bi[g*HH+u] + bh[g*HH+u];
  }
}

// ---------------- role bodies (vbid = row-tile; warp = batch-group) --------
__device__ void lstm0_body(const float* __restrict__ Wh, int t, int rp, int vbid)
{
  int u = vbid;                         // 512 blocks, 1 unit each
  int b0 = (threadIdx.x >> 5) * 4;      // warp = batch-group
  ZACC16
  wgemv16(g_h0[rp], HH, b0,
          Wh + (size_t)(0*HH+u)*HH, Wh + (size_t)(1*HH+u)*HH,
          Wh + (size_t)(2*HH+u)*HH, Wh + (size_t)(3*HH+u)*HH, HH, acc);
  RED16
  int lane = threadIdx.x & 31;
  if (lane < 4){
    int b = b0 + lane;
    const float* xg = g_xg + ((size_t)b*TT + t)*(4*HH);
    float gi = r[lane*4+0] + xg[0*HH+u];
    float gf = r[lane*4+1] + xg[1*HH+u];
    float gg = r[lane*4+2] + xg[2*HH+u];
    float go = r[lane*4+3] + xg[3*HH+u];
    int ci = b*HH + u;
    float c2 = sigm(gf)*g_c0[ci] + sigm(gi)*tanhf(gg);
    g_c0[ci] = c2;
    g_h0[1-rp][ci] = sigm(go)*tanhf(c2);
  }
}

__device__ void lstm1_body(const float* __restrict__ Wi, const float* __restrict__ bi,
    const float* __restrict__ Wh, const float* __restrict__ bh, int rp, int vbid)
{
  int u = vbid;                         // 512 blocks
  int b0 = (threadIdx.x >> 5) * 4;
  ZACC16
  wgemv16(g_h0[1-rp], HH, b0,
          Wi + (size_t)(0*HH+u)*HH, Wi + (size_t)(1*HH+u)*HH,
          Wi + (size_t)(2*HH+u)*HH, Wi + (size_t)(3*HH+u)*HH, HH, acc);
  wgemv16(g_h1[rp], HH, b0,
          Wh + (size_t)(0*HH+u)*HH, Wh + (size_t)(1*HH+u)*HH,
          Wh + (size_t)(2*HH+u)*HH, Wh + (size_t)(3*HH+u)*HH, HH, acc);
  RED16
  int lane = threadIdx.x & 31;
  if (lane < 4){
    int b = b0 + lane;
    float gi = r[lane*4+0] + bi[0*HH+u] + bh[0*HH+u];
    float gf = r[lane*4+1] + bi[1*HH+u] + bh[1*HH+u];
    float gg = r[lane*4+2] + bi[2*HH+u] + bh[2*HH+u];
    float go = r[lane*4+3] + bi[3*HH+u] + bh[3*HH+u];
    int ci = b*HH + u;
    float c2 = sigm(gf)*g_c1[ci] + sigm(gi)*tanhf(gg);
    g_c1[ci] = c2;
    g_h1[1-rp][ci] = sigm(go)*tanhf(c2);
  }
}

__device__ void iface_body(const float* __restrict__ Wif, const float* __restrict__ bif,
    const float* __restrict__ Wmo, const float* __restrict__ bmo, int rp, int vbid)
{
  int rb = vbid*4;                      // 246 blocks, 4 rows each
  int b0 = (threadIdx.x >> 5) * 4;
  int rr4[4]; const float* rp_[4];
  #pragma unroll
  for (int j=0;j<4;j++){
    int rrow = rb + j; if (rrow > NIF-1) rrow = NIF-1;
    rr4[j] = rrow;
    rp_[j] = (rrow < IFACE) ? (Wif + (size_t)rrow*HH) : (Wmo + (size_t)(rrow-IFACE)*HH);
  }
  ZACC16
  wgemv16(g_h1[1-rp], HH, b0, rp_[0], rp_[1], rp_[2], rp_[3], HH, acc);
  RED16
  int lane = threadIdx.x & 31;
  if (lane < 4){
    int b = b0 + lane;
    #pragma unroll
    for (int j=0;j<4;j++){
      int row = rr4[j];
      float val = r[lane*4+j] + ((row < IFACE) ? bif[row] : bmo[row-IFACE]);
      if (row < IFACE) g_v[b*IFACE + row] = val;
      else             g_outbuf[rp][b*HH + (row-IFACE)] = val;
    }
  }
}

// rv(t-1): reads rw written by rw2(t-1) = g_rw[1-rp_prev].
__device__ void rv_body(int rp_prev, int br)
{
  __shared__ float part[4][64];
  int tt = threadIdx.x, w = tt & 63, mq = tt >> 6;
  int b = br >> 2;
  const float* rwn = g_rw[1-rp_prev] + br*MM;
  const float* mb = g_mem + (size_t)b*MM*WWID;
  float acc = 0.f;
  #pragma unroll 8
  for (int m2 = mq*64; m2 < mq*64+64; m2++) acc += rwn[m2]*mb[(size_t)m2*WWID + w];
  part[mq][w] = acc;
  __syncthreads();
  if (mq == 0) g_rvbuf[br*WWID + w] = part[0][w]+part[1][w]+part[2][w]+part[3][w];
}

__device__ void wrv_body(const float* __restrict__ Wrv, const float* __restrict__ brv,
    int rp_prev, int vbid)
{
  int rb = vbid*4;                      // 128 blocks
  int b0 = (threadIdx.x >> 5) * 4;
  ZACC16
  wgemv16(g_rvbuf, RR*WWID, b0,
          Wrv + (size_t)(rb+0)*(RR*WWID), Wrv + (size_t)(rb+1)*(RR*WWID),
          Wrv + (size_t)(rb+2)*(RR*WWID), Wrv + (size_t)(rb+3)*(RR*WWID),
          RR*WWID, acc);
  RED16
  int lane = threadIdx.x & 31;
  if (lane < 4){
    int b = b0 + lane;
    #pragma unroll
    for (int j=0;j<4;j++){
      int row = rb + j;
      g_out2[b*HH + row] = r[lane*4+j] + brv[row] + g_outbuf[rp_prev][b*HH + row];
    }
  }
}

__device__ void wout_body(const float* __restrict__ Wout, const float* __restrict__ bout,
    float* __restrict__ y, int tprev, int vbid)
{
  int rb = vbid*4;                      // 64 blocks
  int b0 = (threadIdx.x >> 5) * 4;
  ZACC16
  wgemv16(g_out2, HH, b0,
          Wout + (size_t)(rb+0)*HH, Wout + (size_t)(rb+1)*HH,
          Wout + (size_t)(rb+2)*HH, Wout + (size_t)(rb+3)*HH, HH, acc);
  RED16
  int lane = threadIdx.x & 31;
  if (lane < 4){
    int b = b0 + lane;
    #pragma unroll
    for (int j=0;j<4;j++){
      int row = rb + j;
      y[((size_t)b*TT + tprev)*DIN + row] = r[lane*4+j] + bout[row];
    }
  }
}

// ---------------- block reductions ----------------
__device__ __forceinline__ float blkmax(float v, volatile float* s8){
  #pragma unroll
  for (int o=16;o;o>>=1) v = fmaxf(v, __shfl_xor_sync(0xffffffffu, v, o));
  if ((threadIdx.x & 31)==0) s8[threadIdx.x>>5] = v;
  __syncthreads();
  float rr = s8[0];
  #pragma unroll
  for (int i=1;i<8;i++) rr = fmaxf(rr, s8[i]);
  __syncthreads();
  return rr;
}
__device__ __forceinline__ float blksum(float v, volatile float* s8){
  #pragma unroll
  for (int o=16;o;o>>=1) v += __shfl_xor_sync(0xffffffffu, v, o);
  if ((threadIdx.x & 31)==0) s8[threadIdx.x>>5] = v;
  __syncthreads();
  float rr = 0.f;
  #pragma unroll
  for (int i=0;i<8;i++) rr += s8[i];
  __syncthreads();
  return rr;
}

// ---- fused memory module ----
__device__ void mem1_body(int rp, int b)
{
  __shared__ float swk[WWID], ser[WWID], swv[WWID], srk[RR*WWID];
  __shared__ float s8[8];
  __shared__ float skey[MM]; __shared__ int sidx[MM];
  __shared__ float sprod[MM], salloc[MM];
  __shared__ float sc[12];
  int m = threadIdx.x;
  const float* vb = g_v + b*IFACE;
  if (m < WWID){ swk[m]=tanhf(vb[WK_OFF+m]); ser[m]=sigm(vb[ER_OFF+m]); swv[m]=tanhf(vb[WV_OFF+m]); }
  srk[m] = tanhf(vb[RK_OFF + m]);
  __syncthreads();
  if (m == 0){
    float s=0.f; for (int w=0;w<WWID;w++) s += swk[w]*swk[w];
    sc[0]=sqrtf(s)+EPSV; sc[1]=softplusf(vb[WS_OFF]);
    sc[10]=sigm(vb[AG_OFF]); sc[11]=sigm(vb[WG_OFF]);
  }
  if (m >= 32 && m < 36){
    int rh = m-32; float s=0.f;
    for (int w=0;w<WWID;w++) s += srk[rh*WWID+w]*srk[rh*WWID+w];
    sc[2+rh]=sqrtf(s)+EPSV; sc[6+rh]=softplusf(vb[RS_OFF+rh]);
  }
  __syncthreads();
  float4 mrow[16];
  float4* mr = (float4*)(g_mem + (size_t)(b*MM+m)*WWID);
  #pragma unroll
  for (int i=0;i<16;i++) mrow[i] = mr[i];
  const float* rwp = g_rw[rp] + b*RR*MM;
  float psi = 1.f;
  #pragma unroll
  for (int rh=0;rh<RR;rh++) psi *= (1.f - sigm(vb[FG_OFF+rh])*rwp[rh*MM+m]);
  float us = g_usage[b*MM+m], wwp = g_ww[b*MM+m];
  us = (us + (1.f-us)*wwp)*psi;
  float dot = 0.f;
  #pragma unroll
  for (int i=0;i<16;i++)
    dot += mrow[i].x*swk[4*i] + mrow[i].y*swk[4*i+1] + mrow[i].z*swk[4*i+2] + mrow[i].w*swk[4*i+3];
  float score = dot/((g_memnorm[b*MM+m]+EPSV)*sc[0]) * sc[1];
  float mx = blkmax(score, s8);
  float e  = expf(score - mx);
  float sm = blksum(e, s8);
  float cww = e/sm;
  float uval = EPSV + (1.f-EPSV)*us;
  skey[m]=uval; sidx[m]=m; __syncthreads();
  for (int k=2;k<=MM;k<<=1){
    for (int j=k>>1;j>0;j>>=1){
      int p = m ^ j;
      if (p > m){
        float ka=skey[m], kb=skey[p]; int ia=sidx[m], ib=sidx[p];
        bool agtb = (ka>kb)||(ka==kb&&ia>ib);
        bool up = ((m & k)==0);
        if (up==agtb){ skey[m]=kb;skey[p]=ka;sidx[m]=ib;sidx[p]=ia; }
      }
      __syncthreads();
    }
  }
  sprod[m]=skey[m]; __syncthreads();
  for (int off=1;off<MM;off<<=1){
    float tv = (m>=off)? sprod[m-off] : 1.f;
    __syncthreads();
    sprod[m] *= tv;
    __syncthreads();
  }
  salloc[sidx[m]] = (1.f - skey[m]) * ((m==0)?1.f:sprod[m-1]);
  __syncthreads();
  float wwv = sc[11]*(sc[10]*salloc[m] + (1.f-sc[10])*cww);
  g_ww[b*MM+m] = wwv;
  g_usage[b*MM+m] = us;
  float wsum = blksum(wwv, s8);
  if (m==0) g_wwsum[b] = wsum;
  float nrm=0.f, d0=0.f, d1=0.f, d2=0.f, d3=0.f;
  #pragma unroll
  for (int i=0;i<16;i++){
    float4 mv = mrow[i];
    int w0 = 4*i;
    mv.x = mv.x*(1.f - wwv*ser[w0  ]) + wwv*swv[w0  ];
    mv.y = mv.y*(1.f - wwv*ser[w0+1]) + wwv*swv[w0+1];
    mv.z = mv.z*(1.f - wwv*ser[w0+2]) + wwv*swv[w0+2];
    mv.w = mv.w*(1.f - wwv*ser[w0+3]) + wwv*swv[w0+3];
    nrm += mv.x*mv.x + mv.y*mv.y + mv.z*mv.z + mv.w*mv.w;
    d0 += mv.x*srk[0*WWID+w0] + mv.y*srk[0*WWID+w0+1] + mv.z*srk[0*WWID+w0+2] + mv.w*srk[0*WWID+w0+3];
    d1 += mv.x*srk[1*WWID+w0] + mv.y*srk[1*WWID+w0+1] + mv.z*srk[1*WWID+w0+2] + mv.w*srk[1*WWID+w0+3];
    d2 += mv.x*srk[2*WWID+w0] + mv.y*srk[2*WWID+w0+1] + mv.z*srk[2*WWID+w0+2] + mv.w*srk[2*WWID+w0+3];
    d3 += mv.x*srk[3*WWID+w0] + mv.y*srk[3*WWID+w0+1] + mv.z*srk[3*WWID+w0+2] + mv.w*srk[3*WWID+w0+3];
    mr[i] = mv;
  }
  float mn = sqrtf(nrm);
  g_memnorm[b*MM+m] = mn;
  float mne = mn + EPSV;
  float dd[4] = {d0,d1,d2,d3};
  #pragma unroll
  for (int rh=0;rh<RR;rh++){
    float sr = dd[rh]/(mne*sc[2+rh]) * sc[6+rh];
    float mx2 = blkmax(sr, s8);
    float e2 = expf(sr - mx2);
    float s2 = blksum(e2, s8);
    g_cwr[(b*RR+rh)*MM+m] = e2/s2;
  }
}

// ---- fused link update + fwd/bwd + read weights + prec ----
__device__ void rw2_body(int rp, int blk)
{
  __shared__ float srw[RR][MM];
  __shared__ float sww[MM], sprec[MM];
  __shared__ float ft[64][65];
  __shared__ float bt[64][64];
  __shared__ float fpart[4][64][RR];
  __shared__ float bpart[4][64][RR];
  int b = blk >> 2, ig = blk & 3;
  int t = threadIdx.x;
  int I0 = ig*64;
  const float* rwp = g_rw[rp] + b*RR*MM;
  #pragma unroll
  for (int rh=0;rh<RR;rh++) srw[rh][t] = rwp[rh*MM+t];
  sww[t] = g_ww[b*MM+t];
  sprec[t] = g_prec[rp][b*MM+t];
  __syncthreads();

  const float* lold = g_link[rp]   + (size_t)b*MM*MM;
  float*       lnew = g_link[1-rp] + (size_t)b*MM*MM;
  int il2 = t & 63, q2 = t >> 6;
  float fa[RR] = {0.f,0.f,0.f,0.f};
  float ba[RR] = {0.f,0.f,0.f,0.f};

  for (int jq = 0; jq < 4; jq++){
    int J0 = jq*64;
    #pragma unroll
    for (int p = 0; p < 16; p++){
      int e = p*256 + t;
      int il = e >> 6, jl = e & 63;
      int i = I0 + il, j = J0 + jl;
      float lo = lold[((size_t)i<<8) + j];
      float ln = (i==j) ? 0.f : (1.f - sww[i] - sww[j])*lo + sww[i]*sprec[j];
      lnew[((size_t)i<<8) + j] = ln;
      ft[il][jl] = ln;
    }
    #pragma unroll
    for (int p = 0; p < 16; p++){
      int e = p*256 + t;
      int jl = e >> 6, il = e & 63;
      int i = I0 + il, j = J0 + jl;
      float lo = lold[((size_t)j<<8) + i];
      float ln = (i==j) ? 0.f : (1.f - sww[j] - sww[i])*lo + sww[j]*sprec[i];
      bt[jl][il] = ln;
    }
    __syncthreads();
    #pragma unroll
    for (int jj = 0; jj < 16; jj++){
      int jl = q2*16 + jj;
      float fv = ft[il2][jl];
      float bv = bt[jl][il2];
      float rw0 = srw[0][J0+jl], rw1 = srw[1][J0+jl], rw2v = srw[2][J0+jl], rw3 = srw[3][J0+jl];
      fa[0] += fv*rw0; fa[1] += fv*rw1; fa[2] += fv*rw2v; fa[3] += fv*rw3;
      ba[0] += bv*rw0; ba[1] += bv*rw1; ba[2] += bv*rw2v; ba[3] += bv*rw3;
    }
    __syncthreads();
  }
  #pragma unroll
  for (int rh=0;rh<RR;rh++){ fpart[q2][il2][rh]=fa[rh]; bpart[q2][il2][rh]=ba[rh]; }
  __syncthreads();
  if (t < 64){
    int i = I0 + t;
    const float* vb = g_v + b*IFACE;
    float* rwn = g_rw[1-rp] + b*RR*MM;
    #pragma unroll
    for (int rh=0;rh<RR;rh++){
      float fr = fpart[0][t][rh]+fpart[1][t][rh]+fpart[2][t][rh]+fpart[3][t][rh];
      float wr = bpart[0][t][rh]+bpart[1][t][rh]+bpart[2][t][rh]+bpart[3][t][rh];
      float x0 = vb[RM_OFF+rh*3], x1 = vb[RM_OFF+rh*3+1], x2 = vb[RM_OFF+rh*3+2];
      float mx = fmaxf(x0, fmaxf(x1, x2));
      float e0 = expf(x0-mx), e1 = expf(x1-mx), e2 = expf(x2-mx);
      float inv = 1.f/(e0+e1+e2);
      rwn[rh*MM+i] = (e0*wr + e1*fr + e2*g_cwr[(b*RR+rh)*MM+i])*inv;
    }
    g_prec[1-rp][b*MM+i] = (1.f - g_wwsum[b])*sprec[i] + sww[i];
  }
}

// ---------------- dispatcher kernels (R12 partition) ----------
// kA(t): lstm1(t) [0,512) + lstm0(t+1) [512,1024) + rv(t-1) [1024,1152)
__global__ void __launch_bounds__(256) kA(const float* __restrict__ Wi, const float* __restrict__ bi,
    const float* __restrict__ Wh, const float* __restrict__ bh,
    const float* __restrict__ Wh0, int rp, int tnext, int en_rv, int en_l0)
{
  if (blockIdx.x < 512)       lstm1_body(Wi, bi, Wh, bh, rp, blockIdx.x);
  else if (blockIdx.x < 1024){ if (en_l0) lstm0_body(Wh0, tnext, 1-rp, blockIdx.x - 512); }
  else if (en_rv)             rv_body(1-rp, blockIdx.x - 1024);
}
// kB(t): iface(t) [0,246) + wrv(t-1) [246,374)
__global__ void __launch_bounds__(256) kB(const float* __restrict__ Wif, const float* __restrict__ bif,
    const float* __restrict__ Wmo, const float* __restrict__ bmo,
    const float* __restrict__ Wrv, const float* __restrict__ brv, int rp, int en)
{
  if (blockIdx.x < 246) iface_body(Wif, bif, Wmo, bmo, rp, blockIdx.x);
  else if (en)          wrv_body(Wrv, brv, 1-rp, blockIdx.x - 246);
}
// kC(t): mem1(t) [0,32) + wout(t-1) [32,96)
__global__ void __launch_bounds__(256) kC(const float* __restrict__ Wout, const float* __restrict__ bout,
    float* __restrict__ y, int rp, int tprev, int en)
{
  if (blockIdx.x < 32) mem1_body(rp, blockIdx.x);
  else if (en)         wout_body(Wout, bout, y, tprev, blockIdx.x - 32);
}
__global__ void __launch_bounds__(256) kD(int rp)
{
  rw2_body(rp, blockIdx.x);
}

// prologue / epilogue standalone kernels
__global__ void __launch_bounds__(256) k_lstm0s(const float* __restrict__ Wh, int t, int rp)
{ lstm0_body(Wh, t, rp, blockIdx.x); }
__global__ void __launch_bounds__(256) k_rvs(int rp_prev)
{ rv_body(rp_prev, blockIdx.x); }
__global__ void __launch_bounds__(256) k_wrvs(const float* __restrict__ Wrv, const float* __restrict__ brv, int rp_prev)
{ wrv_body(Wrv, brv, rp_prev, blockIdx.x); }
__global__ void __launch_bounds__(256) k_wouts(const float* __restrict__ Wout, const float* __restrict__ bout,
    float* __restrict__ y, int tprev)
{ wout_body(Wout, bout, y, tprev, blockIdx.x); }

// ---------------- host: single-stream software pipeline (R12 schedule) ------
extern "C" void kernel_launch(void* const* d_in, const int* in_sizes, int n_in,
                              void* d_out, int out_size)
{
  const float* x     = (const float*)d_in[0];
  const float* Wih0  = (const float*)d_in[1];
  const float* bih0  = (const float*)d_in[2];
  const float* Whh0  = (const float*)d_in[3];
  const float* bhh0  = (const float*)d_in[4];
  const float* Wih1  = (const float*)d_in[5];
  const float* bih1  = (const float*)d_in[6];
  const float* Whh1  = (const float*)d_in[7];
  const float* bhh1  = (const float*)d_in[8];
  const float* Wif   = (const float*)d_in[9];
  const float* bif   = (const float*)d_in[10];
  const float* Wmo   = (const float*)d_in[11];
  const float* bmo   = (const float*)d_in[12];
  const float* Wrv   = (const float*)d_in[13];
  const float* brv   = (const float*)d_in[14];
  const float* Wout  = (const float*)d_in[15];
  const float* bout  = (const float*)d_in[16];
  float* y = (float*)d_out;

  k_init<<<(BB*MM*MM)/256, 256>>>();
  k_pregemm<<<(BB*TT/4)*(HH/8), 256>>>(x, Wih0, bih0, bhh0);
  k_lstm0s<<<512, 256>>>(Whh0, 0, 0);     // prologue: lstm0(0)

  for (int t = 0; t < TT; t++){
    int rp = t & 1;
    kA<<<1152, 256>>>(Wih1, bih1, Whh1, bhh1, Whh0, rp, t+1, t > 0, t < TT-1); // lstm1(t)+lstm0(t+1)+rv(t-1)
    kB<<<374, 256>>>(Wif, bif, Wmo, bmo, Wrv, brv, rp, t > 0);                 // iface(t) + wrv(t-1)
    kC<<<96, 256>>>(Wout, bout, y, rp, t-1, t > 0);                            // mem1(t) + wout(t-1)
    kD<<<128, 256>>>(rp);                                                      // rw2(t)
  }
  // epilogue: tail of t = TT-1  (rp_prev = (TT-1)&1 = 1)
  k_rvs<<<128, 256>>>(1);
  k_wrvs<<<128, 256>>>(Wrv, brv, 1);
  k_wouts<<<64, 256>>>(Wout, bout, y, TT-1);
}

// round 15
// speedup vs baseline: 1.2660x; 1.0435x over previous
#include <cuda_runtime.h>
#include <math.h>

#define BB 32
#define TT 48
#define DIN 256
#define HH 512
#define MM 256
#define WWID 64
#define RR 4
#define IFACE 471
#define NIF 983
#define EPSV 1e-6f

#define RK_OFF 0
#define RS_OFF 256
#define WK_OFF 260
#define WS_OFF 324
#define ER_OFF 325
#define WV_OFF 389
#define FG_OFF 453
#define AG_OFF 457
#define WG_OFF 458
#define RM_OFF 459

// -------- state --------
__device__ float g_h0[2][BB*HH];
__device__ float g_c0[BB*HH];
__device__ float g_h1[2][BB*HH];
__device__ float g_c1[BB*HH];
__device__ float g_mem[BB*MM*WWID];
__device__ float g_link[2][(size_t)BB*MM*MM];
__device__ float g_prec[2][BB*MM];
__device__ float g_rw[2][BB*RR*MM];
__device__ float g_ww[BB*MM];
__device__ float g_usage[BB*MM];
__device__ float g_memnorm[BB*MM];
__device__ float g_v[BB*IFACE];
__device__ float g_cwr[BB*RR*MM];
__device__ float g_wwsum[BB];
__device__ float g_outbuf[2][BB*HH];     // parity double-buffered
__device__ float g_rvbuf[BB*RR*WWID];
__device__ float g_out2[BB*HH];
__device__ float g_xg[(size_t)BB*TT*4*HH];

__device__ __forceinline__ float sigm(float x){ return 1.f/(1.f+expf(-x)); }
__device__ __forceinline__ float softplusf(float x){ return fmaxf(x,0.f) + log1pf(expf(-fabsf(x))); }
__device__ __forceinline__ float redw(float s){
  #pragma unroll
  for (int o=16;o;o>>=1) s += __shfl_xor_sync(0xffffffffu, s, o);
  return s;
}

// ---------------- init ----------------
__global__ void k_init(){
  size_t i = (size_t)blockIdx.x*blockDim.x + threadIdx.x;
  if (i < (size_t)BB*MM*MM){ g_link[0][i]=0.f; g_link[1][i]=0.f; }
  if (i < BB*MM*WWID) g_mem[i] = 0.f;
  if (i < BB*RR*MM){ g_rw[0][i]=0.f; g_rw[1][i]=0.f; }
  if (i < BB*HH){ g_h0[0][i]=0.f; g_h0[1][i]=0.f; g_c0[i]=0.f;
                  g_h1[0][i]=0.f; g_h1[1][i]=0.f; g_c1[i]=0.f; }
  if (i < BB*MM){ g_prec[0][i]=0.f; g_prec[1][i]=0.f; g_ww[i]=0.f; g_usage[i]=0.f; g_memnorm[i]=0.f; }
}

// ====== warp-GEMV: 4 batches x 4 rows per warp, scalar accumulators ======
// (R12 mapping: block = 8 consecutive row-tiles of one batch-group; x shared
//  via L1 within the block. #pragma unroll 4 forces full unroll of the k-loop
//  so all loads of a GEMV are in flight at once.)
#define FMA4S(A,V,W) { A += (V).x*(W).x; A += (V).y*(W).y; A += (V).z*(W).z; A += (V).w*(W).w; }

__device__ __forceinline__ void wgemv16(
    const float* __restrict__ X, int xld, int b0,
    const float* __restrict__ r0, const float* __restrict__ r1,
    const float* __restrict__ r2, const float* __restrict__ r3,
    int K, float acc[16])
{
  const int lane = threadIdx.x & 31;
  const float4* x0 = (const float4*)(X + (size_t)(b0+0)*xld);
  const float4* x1 = (const float4*)(X + (size_t)(b0+1)*xld);
  const float4* x2 = (const float4*)(X + (size_t)(b0+2)*xld);
  const float4* x3 = (const float4*)(X + (size_t)(b0+3)*xld);
  const float4* w0 = (const float4*)r0;
  const float4* w1 = (const float4*)r1;
  const float4* w2 = (const float4*)r2;
  const float4* w3 = (const float4*)r3;
  const int K4 = K >> 2;
  #pragma unroll 4
  for (int k = lane; k < K4; k += 32){
    float4 a = x0[k], b = x1[k], c = x2[k], d = x3[k];
    float4 wv;
    wv = w0[k]; FMA4S(acc[0],a,wv)  FMA4S(acc[4],b,wv)  FMA4S(acc[8],c,wv)  FMA4S(acc[12],d,wv)
    wv = w1[k]; FMA4S(acc[1],a,wv)  FMA4S(acc[5],b,wv)  FMA4S(acc[9],c,wv)  FMA4S(acc[13],d,wv)
    wv = w2[k]; FMA4S(acc[2],a,wv)  FMA4S(acc[6],b,wv)  FMA4S(acc[10],c,wv) FMA4S(acc[14],d,wv)
    wv = w3[k]; FMA4S(acc[3],a,wv)  FMA4S(acc[7],b,wv)  FMA4S(acc[11],c,wv) FMA4S(acc[15],d,wv)
  }
}
#define ZACC16 float acc[16]; _Pragma("unroll") for (int i_=0;i_<16;i_++) acc[i_]=0.f;
#define RED16  float r[16];   _Pragma("unroll") for (int i_=0;i_<16;i_++) r[i_]=redw(acc[i_]);

// ---------------- pregemm (one-time) ----------------
__global__ void __launch_bounds__(256) k_pregemm(const float* __restrict__ x,
    const float* __restrict__ Wi, const float* __restrict__ bi, const float* __restrict__ bh)
{
  int gw = blockIdx.x*8 + (threadIdx.x>>5);
  int ng = gw >> 9, u = gw & 511;
  int n0 = ng*4;
  ZACC16
  wgemv16(x, DIN, n0,
          Wi + (size_t)(0*HH+u)*DIN, Wi + (size_t)(1*HH+u)*DIN,
          Wi + (size_t)(2*HH+u)*DIN, Wi + (size_t)(3*HH+u)*DIN, DIN, acc);
  RED16
  int lane = threadIdx.x & 31;
  if (lane < 4){
    int n = n0 + lane;
    #pragma unroll
    for (int g=0; g<4; g++)
      g_xg[(size_t)n*(4*HH) + g*HH + u] = r[lane*4+g] + bi[g*HH+u] + bh[g*HH+u];
  }
}

// ---------------- role bodies (R12 mapping) ----------------
__device__ void lstm0_body(const float* __restrict__ Wh, int t, int rp, int vbid)
{
  int gw = vbid*8 + (threadIdx.x>>5);
  int bg = gw >> 9, u = gw & 511;
  int b0 = bg*4;
  ZACC16
  wgemv16(g_h0[rp], HH, b0,
          Wh + (size_t)(0*HH+u)*HH, Wh + (size_t)(1*HH+u)*HH,
          Wh + (size_t)(2*HH+u)*HH, Wh + (size_t)(3*HH+u)*HH, HH, acc);
  RED16
  int lane = threadIdx.x & 31;
  if (lane < 4){
    int b = b0 + lane;
    const float* xg = g_xg + ((size_t)b*TT + t)*(4*HH);
    float gi = r[lane*4+0] + xg[0*HH+u];
    float gf = r[lane*4+1] + xg[1*HH+u];
    float gg = r[lane*4+2] + xg[2*HH+u];
    float go = r[lane*4+3] + xg[3*HH+u];
    int ci = b*HH + u;
    float c2 = sigm(gf)*g_c0[ci] + sigm(gi)*tanhf(gg);
    g_c0[ci] = c2;
    g_h0[1-rp][ci] = sigm(go)*tanhf(c2);
  }
}

__device__ void lstm1_body(const float* __restrict__ Wi, const float* __restrict__ bi,
    const float* __restrict__ Wh, const float* __restrict__ bh, int rp, int vbid)
{
  int gw = vbid*8 + (threadIdx.x>>5);
  int bg = gw >> 9, u = gw & 511;
  int b0 = bg*4;
  ZACC16
  wgemv16(g_h0[1-rp], HH, b0,
          Wi + (size_t)(0*HH+u)*HH, Wi + (size_t)(1*HH+u)*HH,
          Wi + (size_t)(2*HH+u)*HH, Wi + (size_t)(3*HH+u)*HH, HH, acc);
  wgemv16(g_h1[rp], HH, b0,
          Wh + (size_t)(0*HH+u)*HH, Wh + (size_t)(1*HH+u)*HH,
          Wh + (size_t)(2*HH+u)*HH, Wh + (size_t)(3*HH+u)*HH, HH, acc);
  RED16
  int lane = threadIdx.x & 31;
  if (lane < 4){
    int b = b0 + lane;
    float gi = r[lane*4+0] + bi[0*HH+u] + bh[0*HH+u];
    float gf = r[lane*4+1] + bi[1*HH+u] + bh[1*HH+u];
    float gg = r[lane*4+2] + bi[2*HH+u] + bh[2*HH+u];
    float go = r[lane*4+3] + bi[3*HH+u] + bh[3*HH+u];
    int ci = b*HH + u;
    float c2 = sigm(gf)*g_c1[ci] + sigm(gi)*tanhf(gg);
    g_c1[ci] = c2;
    g_h1[1-rp][ci] = sigm(go)*tanhf(c2);
  }
}

__device__ void iface_body(const float* __restrict__ Wif, const float* __restrict__ bif,
    const float* __restrict__ Wmo, const float* __restrict__ bmo, int rp, int vbid)
{
  int gw = vbid*8 + (threadIdx.x>>5);          // 1968 warps = 8 bg x 246 rg
  int bg = gw / 246, rg = gw % 246;
  int b0 = bg*4, rb = rg*4;
  int rr4[4]; const float* rp_[4];
  #pragma unroll
  for (int j=0;j<4;j++){
    int rrow = rb + j; if (rrow > NIF-1) rrow = NIF-1;
    rr4[j] = rrow;
    rp_[j] = (rrow < IFACE) ? (Wif + (size_t)rrow*HH) : (Wmo + (size_t)(rrow-IFACE)*HH);
  }
  ZACC16
  wgemv16(g_h1[1-rp], HH, b0, rp_[0], rp_[1], rp_[2], rp_[3], HH, acc);
  RED16
  int lane = threadIdx.x & 31;
  if (lane < 4){
    int b = b0 + lane;
    #pragma unroll
    for (int j=0;j<4;j++){
      int row = rr4[j];
      float val = r[lane*4+j] + ((row < IFACE) ? bif[row] : bmo[row-IFACE]);
      if (row < IFACE) g_v[b*IFACE + row] = val;
      else             g_outbuf[rp][b*HH + (row-IFACE)] = val;
    }
  }
}

// rv(t-1): reads rw written by rw2(t-1) = g_rw[1-rp_prev].
__device__ void rv_body(int rp_prev, int br)
{
  __shared__ float part[4][64];
  int tt = threadIdx.x, w = tt & 63, mq = tt >> 6;
  int b = br >> 2;
  const float* rwn = g_rw[1-rp_prev] + br*MM;
  const float* mb = g_mem + (size_t)b*MM*WWID;
  float acc = 0.f;
  #pragma unroll 8
  for (int m2 = mq*64; m2 < mq*64+64; m2++) acc += rwn[m2]*mb[(size_t)m2*WWID + w];
  part[mq][w] = acc;
  __syncthreads();
  if (mq == 0) g_rvbuf[br*WWID + w] = part[0][w]+part[1][w]+part[2][w]+part[3][w];
}

__device__ void wrv_body(const float* __restrict__ Wrv, const float* __restrict__ brv,
    int rp_prev, int vbid)
{
  int gw = vbid*8 + (threadIdx.x>>5);   // 1024 warps
  int bg = gw >> 7, rg = gw & 127;
  int b0 = bg*4, rb = rg*4;
  ZACC16
  wgemv16(g_rvbuf, RR*WWID, b0,
          Wrv + (size_t)(rb+0)*(RR*WWID), Wrv + (size_t)(rb+1)*(RR*WWID),
          Wrv + (size_t)(rb+2)*(RR*WWID), Wrv + (size_t)(rb+3)*(RR*WWID),
          RR*WWID, acc);
  RED16
  int lane = threadIdx.x & 31;
  if (lane < 4){
    int b = b0 + lane;
    #pragma unroll
    for (int j=0;j<4;j++){
      int row = rb + j;
      g_out2[b*HH + row] = r[lane*4+j] + brv[row] + g_outbuf[rp_prev][b*HH + row];
    }
  }
}

__device__ void wout_body(const float* __restrict__ Wout, const float* __restrict__ bout,
    float* __restrict__ y, int tprev, int vbid)
{
  int gw = vbid*8 + (threadIdx.x>>5);   // 512 warps
  int bg = gw >> 6, rg = gw & 63;
  int b0 = bg*4, rb = rg*4;
  ZACC16
  wgemv16(g_out2, HH, b0,
          Wout + (size_t)(rb+0)*HH, Wout + (size_t)(rb+1)*HH,
          Wout + (size_t)(rb+2)*HH, Wout + (size_t)(rb+3)*HH, HH, acc);
  RED16
  int lane = threadIdx.x & 31;
  if (lane < 4){
    int b = b0 + lane;
    #pragma unroll
    for (int j=0;j<4;j++){
      int row = rb + j;
      y[((size_t)b*TT + tprev)*DIN + row] = r[lane*4+j] + bout[row];
    }
  }
}

// ---------------- block reductions ----------------
__device__ __forceinline__ float blkmax(float v, volatile float* s8){
  #pragma unroll
  for (int o=16;o;o>>=1) v = fmaxf(v, __shfl_xor_sync(0xffffffffu, v, o));
  if ((threadIdx.x & 31)==0) s8[threadIdx.x>>5] = v;
  __syncthreads();
  float rr = s8[0];
  #pragma unroll
  for (int i=1;i<8;i++) rr = fmaxf(rr, s8[i]);
  __syncthreads();
  return rr;
}
__device__ __forceinline__ float blksum(float v, volatile float* s8){
  #pragma unroll
  for (int o=16;o;o>>=1) v += __shfl_xor_sync(0xffffffffu, v, o);
  if ((threadIdx.x & 31)==0) s8[threadIdx.x>>5] = v;
  __syncthreads();
  float rr = 0.f;
  #pragma unroll
  for (int i=0;i<8;i++) rr += s8[i];
  __syncthreads();
  return rr;
}

// ---- fused memory module ----
__device__ void mem1_body(int rp, int b)
{
  __shared__ float swk[WWID], ser[WWID], swv[WWID], srk[RR*WWID];
  __shared__ float s8[8];
  __shared__ float skey[MM]; __shared__ int sidx[MM];
  __shared__ float sprod[MM], salloc[MM];
  __shared__ float sc[12];
  int m = threadIdx.x;
  const float* vb = g_v + b*IFACE;
  if (m < WWID){ swk[m]=tanhf(vb[WK_OFF+m]); ser[m]=sigm(vb[ER_OFF+m]); swv[m]=tanhf(vb[WV_OFF+m]); }
  srk[m] = tanhf(vb[RK_OFF + m]);
  __syncthreads();
  if (m == 0){
    float s=0.f; for (int w=0;w<WWID;w++) s += swk[w]*swk[w];
    sc[0]=sqrtf(s)+EPSV; sc[1]=softplusf(vb[WS_OFF]);
    sc[10]=sigm(vb[AG_OFF]); sc[11]=sigm(vb[WG_OFF]);
  }
  if (m >= 32 && m < 36){
    int rh = m-32; float s=0.f;
    for (int w=0;w<WWID;w++) s += srk[rh*WWID+w]*srk[rh*WWID+w];
    sc[2+rh]=sqrtf(s)+EPSV; sc[6+rh]=softplusf(vb[RS_OFF+rh]);
  }
  __syncthreads();
  float4 mrow[16];
  float4* mr = (float4*)(g_mem + (size_t)(b*MM+m)*WWID);
  #pragma unroll
  for (int i=0;i<16;i++) mrow[i] = mr[i];
  const float* rwp = g_rw[rp] + b*RR*MM;
  float psi = 1.f;
  #pragma unroll
  for (int rh=0;rh<RR;rh++) psi *= (1.f - sigm(vb[FG_OFF+rh])*rwp[rh*MM+m]);
  float us = g_usage[b*MM+m], wwp = g_ww[b*MM+m];
  us = (us + (1.f-us)*wwp)*psi;
  float dot = 0.f;
  #pragma unroll
  for (int i=0;i<16;i++)
    dot += mrow[i].x*swk[4*i] + mrow[i].y*swk[4*i+1] + mrow[i].z*swk[4*i+2] + mrow[i].w*swk[4*i+3];
  float score = dot/((g_memnorm[b*MM+m]+EPSV)*sc[0]) * sc[1];
  float mx = blkmax(score, s8);
  float e  = expf(score - mx);
  float sm = blksum(e, s8);
  float cww = e/sm;
  float uval = EPSV + (1.f-EPSV)*us;
  skey[m]=uval; sidx[m]=m; __syncthreads();
  for (int k=2;k<=MM;k<<=1){
    for (int j=k>>1;j>0;j>>=1){
      int p = m ^ j;
      if (p > m){
        float ka=skey[m], kb=skey[p]; int ia=sidx[m], ib=sidx[p];
        bool agtb = (ka>kb)||(ka==kb&&ia>ib);
        bool up = ((m & k)==0);
        if (up==agtb){ skey[m]=kb;skey[p]=ka;sidx[m]=ib;sidx[p]=ia; }
      }
      __syncthreads();
    }
  }
  sprod[m]=skey[m]; __syncthreads();
  for (int off=1;off<MM;off<<=1){
    float tv = (m>=off)? sprod[m-off] : 1.f;
    __syncthreads();
    sprod[m] *= tv;
    __syncthreads();
  }
  salloc[sidx[m]] = (1.f - skey[m]) * ((m==0)?1.f:sprod[m-1]);
  __syncthreads();
  float wwv = sc[11]*(sc[10]*salloc[m] + (1.f-sc[10])*cww);
  g_ww[b*MM+m] = wwv;
  g_usage[b*MM+m] = us;
  float wsum = blksum(wwv, s8);
  if (m==0) g_wwsum[b] = wsum;
  float nrm=0.f, d0=0.f, d1=0.f, d2=0.f, d3=0.f;
  #pragma unroll
  for (int i=0;i<16;i++){
    float4 mv = mrow[i];
    int w0 = 4*i;
    mv.x = mv.x*(1.f - wwv*ser[w0  ]) + wwv*swv[w0  ];
    mv.y = mv.y*(1.f - wwv*ser[w0+1]) + wwv*swv[w0+1];
    mv.z = mv.z*(1.f - wwv*ser[w0+2]) + wwv*swv[w0+2];
    mv.w = mv.w*(1.f - wwv*ser[w0+3]) + wwv*swv[w0+3];
    nrm += mv.x*mv.x + mv.y*mv.y + mv.z*mv.z + mv.w*mv.w;
    d0 += mv.x*srk[0*WWID+w0] + mv.y*srk[0*WWID+w0+1] + mv.z*srk[0*WWID+w0+2] + mv.w*srk[0*WWID+w0+3];
    d1 += mv.x*srk[1*WWID+w0] + mv.y*srk[1*WWID+w0+1] + mv.z*srk[1*WWID+w0+2] + mv.w*srk[1*WWID+w0+3];
    d2 += mv.x*srk[2*WWID+w0] + mv.y*srk[2*WWID+w0+1] + mv.z*srk[2*WWID+w0+2] + mv.w*srk[2*WWID+w0+3];
    d3 += mv.x*srk[3*WWID+w0] + mv.y*srk[3*WWID+w0+1] + mv.z*srk[3*WWID+w0+2] + mv.w*srk[3*WWID+w0+3];
    mr[i] = mv;
  }
  float mn = sqrtf(nrm);
  g_memnorm[b*MM+m] = mn;
  float mne = mn + EPSV;
  float dd[4] = {d0,d1,d2,d3};
  #pragma unroll
  for (int rh=0;rh<RR;rh++){
    float sr = dd[rh]/(mne*sc[2+rh]) * sc[6+rh];
    float mx2 = blkmax(sr, s8);
    float e2 = expf(sr - mx2);
    float s2 = blksum(e2, s8);
    g_cwr[(b*RR+rh)*MM+m] = e2/s2;
  }
}

// ---- fused link update + fwd/bwd + read weights + prec ----
__device__ void rw2_body(int rp, int blk)
{
  __shared__ float srw[RR][MM];
  __shared__ float sww[MM], sprec[MM];
  __shared__ float ft[64][65];
  __shared__ float bt[64][64];
  __shared__ float fpart[4][64][RR];
  __shared__ float bpart[4][64][RR];
  int b = blk >> 2, ig = blk & 3;
  int t = threadIdx.x;
  int I0 = ig*64;
  const float* rwp = g_rw[rp] + b*RR*MM;
  #pragma unroll
  for (int rh=0;rh<RR;rh++) srw[rh][t] = rwp[rh*MM+t];
  sww[t] = g_ww[b*MM+t];
  sprec[t] = g_prec[rp][b*MM+t];
  __syncthreads();

  const float* lold = g_link[rp]   + (size_t)b*MM*MM;
  float*       lnew = g_link[1-rp] + (size_t)b*MM*MM;
  int il2 = t & 63, q2 = t >> 6;
  float fa[RR] = {0.f,0.f,0.f,0.f};
  float ba[RR] = {0.f,0.f,0.f,0.f};

  for (int jq = 0; jq < 4; jq++){
    int J0 = jq*64;
    #pragma unroll
    for (int p = 0; p < 16; p++){
      int e = p*256 + t;
      int il = e >> 6, jl = e & 63;
      int i = I0 + il, j = J0 + jl;
      float lo = lold[((size_t)i<<8) + j];
      float ln = (i==j) ? 0.f : (1.f - sww[i] - sww[j])*lo + sww[i]*sprec[j];
      lnew[((size_t)i<<8) + j] = ln;
      ft[il][jl] = ln;
    }
    #pragma unroll
    for (int p = 0; p < 16; p++){
      int e = p*256 + t;
      int jl = e >> 6, il = e & 63;
      int i = I0 + il, j = J0 + jl;
      float lo = lold[((size_t)j<<8) + i];
      float ln = (i==j) ? 0.f : (1.f - sww[j] - sww[i])*lo + sww[j]*sprec[i];
      bt[jl][il] = ln;
    }
    __syncthreads();
    #pragma unroll
    for (int jj = 0; jj < 16; jj++){
      int jl = q2*16 + jj;
      float fv = ft[il2][jl];
      float bv = bt[jl][il2];
      float rw0 = srw[0][J0+jl], rw1 = srw[1][J0+jl], rw2v = srw[2][J0+jl], rw3 = srw[3][J0+jl];
      fa[0] += fv*rw0; fa[1] += fv*rw1; fa[2] += fv*rw2v; fa[3] += fv*rw3;
      ba[0] += bv*rw0; ba[1] += bv*rw1; ba[2] += bv*rw2v; ba[3] += bv*rw3;
    }
    __syncthreads();
  }
  #pragma unroll
  for (int rh=0;rh<RR;rh++){ fpart[q2][il2][rh]=fa[rh]; bpart[q2][il2][rh]=ba[rh]; }
  __syncthreads();
  if (t < 64){
    int i = I0 + t;
    const float* vb = g_v + b*IFACE;
    float* rwn = g_rw[1-rp] + b*RR*MM;
    #pragma unroll
    for (int rh=0;rh<RR;rh++){
      float fr = fpart[0][t][rh]+fpart[1][t][rh]+fpart[2][t][rh]+fpart[3][t][rh];
      float wr = bpart[0][t][rh]+bpart[1][t][rh]+bpart[2][t][rh]+bpart[3][t][rh];
      float x0 = vb[RM_OFF+rh*3], x1 = vb[RM_OFF+rh*3+1], x2 = vb[RM_OFF+rh*3+2];
      float mx = fmaxf(x0, fmaxf(x1, x2));
      float e0 = expf(x0-mx), e1 = expf(x1-mx), e2 = expf(x2-mx);
      float inv = 1.f/(e0+e1+e2);
      rwn[rh*MM+i] = (e0*wr + e1*fr + e2*g_cwr[(b*RR+rh)*MM+i])*inv;
    }
    g_prec[1-rp][b*MM+i] = (1.f - g_wwsum[b])*sprec[i] + sww[i];
  }
}

// ---------------- dispatcher kernels (R12 partition) ----------
// kA(t): lstm1(t) [0,512) + lstm0(t+1) [512,1024) + rv(t-1) [1024,1152)
__global__ void __launch_bounds__(256) kA(const float* __restrict__ Wi, const float* __restrict__ bi,
    const float* __restrict__ Wh, const float* __restrict__ bh,
    const float* __restrict__ Wh0, int rp, int tnext, int en_rv, int en_l0)
{
  if (blockIdx.x < 512)       lstm1_body(Wi, bi, Wh, bh, rp, blockIdx.x);
  else if (blockIdx.x < 1024){ if (en_l0) lstm0_body(Wh0, tnext, 1-rp, blockIdx.x - 512); }
  else if (en_rv)             rv_body(1-rp, blockIdx.x - 1024);
}
// kB(t): iface(t) [0,246) + wrv(t-1) [246,374)
__global__ void __launch_bounds__(256) kB(const float* __restrict__ Wif, const float* __restrict__ bif,
    const float* __restrict__ Wmo, const float* __restrict__ bmo,
    const float* __restrict__ Wrv, const float* __restrict__ brv, int rp, int en)
{
  if (blockIdx.x < 246) iface_body(Wif, bif, Wmo, bmo, rp, blockIdx.x);
  else if (en)          wrv_body(Wrv, brv, 1-rp, blockIdx.x - 246);
}
// kC(t): mem1(t) [0,32) + wout(t-1) [32,96)
__global__ void __launch_bounds__(256) kC(const float* __restrict__ Wout, const float* __restrict__ bout,
    float* __restrict__ y, int rp, int tprev, int en)
{
  if (blockIdx.x < 32) mem1_body(rp, blockIdx.x);
  else if (en)         wout_body(Wout, bout, y, tprev, blockIdx.x - 32);
}
__global__ void __launch_bounds__(256) kD(int rp)
{
  rw2_body(rp, blockIdx.x);
}

// prologue / epilogue standalone kernels
__global__ void __launch_bounds__(256) k_lstm0s(const float* __restrict__ Wh, int t, int rp)
{ lstm0_body(Wh, t, rp, blockIdx.x); }
__global__ void __launch_bounds__(256) k_rvs(int rp_prev)
{ rv_body(rp_prev, blockIdx.x); }
__global__ void __launch_bounds__(256) k_wrvs(const float* __restrict__ Wrv, const float* __restrict__ brv, int rp_prev)
{ wrv_body(Wrv, brv, rp_prev, blockIdx.x); }
__global__ void __launch_bounds__(256) k_wouts(const float* __restrict__ Wout, const float* __restrict__ bout,
    float* __restrict__ y, int tprev)
{ wout_body(Wout, bout, y, tprev, blockIdx.x); }

// ---------------- host: single-stream software pipeline (R12 schedule) ------
extern "C" void kernel_launch(void* const* d_in, const int* in_sizes, int n_in,
                              void* d_out, int out_size)
{
  const float* x     = (const float*)d_in[0];
  const float* Wih0  = (const float*)d_in[1];
  const float* bih0  = (const float*)d_in[2];
  const float* Whh0  = (const float*)d_in[3];
  const float* bhh0  = (const float*)d_in[4];
  const float* Wih1  = (const float*)d_in[5];
  const float* bih1  = (const float*)d_in[6];
  const float* Whh1  = (const float*)d_in[7];
  const float* bhh1  = (const float*)d_in[8];
  const float* Wif   = (const float*)d_in[9];
  const float* bif   = (const float*)d_in[10];
  const float* Wmo   = (const float*)d_in[11];
  const float* bmo   = (const float*)d_in[12];
  const float* Wrv   = (const float*)d_in[13];
  const float* brv   = (const float*)d_in[14];
  const float* Wout  = (const float*)d_in[15];
  const float* bout  = (const float*)d_in[16];
  float* y = (float*)d_out;

  k_init<<<(BB*MM*MM)/256, 256>>>();
  k_pregemm<<<(BB*TT/4)*(HH/8), 256>>>(x, Wih0, bih0, bhh0);
  k_lstm0s<<<512, 256>>>(Whh0, 0, 0);     // prologue: lstm0(0)

  for (int t = 0; t < TT; t++){
    int rp = t & 1;
    kA<<<1152, 256>>>(Wih1, bih1, Whh1, bhh1, Whh0, rp, t+1, t > 0, t < TT-1); // lstm1(t)+lstm0(t+1)+rv(t-1)
    kB<<<374, 256>>>(Wif, bif, Wmo, bmo, Wrv, brv, rp, t > 0);                 // iface(t) + wrv(t-1)
    kC<<<96, 256>>>(Wout, bout, y, rp, t-1, t > 0);                            // mem1(t) + wout(t-1)
    kD<<<128, 256>>>(rp);                                                      // rw2(t)
  }
  // epilogue: tail of t = TT-1  (rp_prev = (TT-1)&1 = 1)
  k_rvs<<<128, 256>>>(1);
  k_wrvs<<<128, 256>>>(Wrv, brv, 1);
  k_wouts<<<64, 256>>>(Wout, bout, y, TT-1);
}

// round 16
// speedup vs baseline: 1.2840x; 1.0142x over previous
#include <cuda_runtime.h>
#include <math.h>

#define BB 32
#define TT 48
#define DIN 256
#define HH 512
#define MM 256
#define WWID 64
#define RR 4
#define IFACE 471
#define NIF 983
#define EPSV 1e-6f

#define RK_OFF 0
#define RS_OFF 256
#define WK_OFF 260
#define WS_OFF 324
#define ER_OFF 325
#define WV_OFF 389
#define FG_OFF 453
#define AG_OFF 457
#define WG_OFF 458
#define RM_OFF 459

// -------- state --------
__device__ float g_h0[2][BB*HH];
__device__ float g_c0[BB*HH];
__device__ float g_h1[2][BB*HH];
__device__ float g_c1[BB*HH];
__device__ float g_mem[BB*MM*WWID];
__device__ float g_link[2][(size_t)BB*MM*MM];
__device__ float g_prec[2][BB*MM];
__device__ float g_rw[2][BB*RR*MM];
__device__ float g_ww[BB*MM];
__device__ float g_usage[BB*MM];
__device__ float g_memnorm[BB*MM];
__device__ float g_v[BB*IFACE];
__device__ float g_cwr[BB*RR*MM];
__device__ float g_wwsum[BB];
__device__ float g_outbuf[2][BB*HH];     // parity double-buffered
__device__ float g_rvbuf[BB*RR*WWID];
__device__ float g_out2[BB*HH];
__device__ float g_xg[(size_t)BB*TT*4*HH];

__device__ __forceinline__ float sigm(float x){ return 1.f/(1.f+expf(-x)); }
__device__ __forceinline__ float softplusf(float x){ return fmaxf(x,0.f) + log1pf(expf(-fabsf(x))); }
__device__ __forceinline__ float redw(float s){
  #pragma unroll
  for (int o=16;o;o>>=1) s += __shfl_xor_sync(0xffffffffu, s, o);
  return s;
}

// ---------------- init ----------------
__global__ void k_init(){
  size_t i = (size_t)blockIdx.x*blockDim.x + threadIdx.x;
  if (i < (size_t)BB*MM*MM){ g_link[0][i]=0.f; g_link[1][i]=0.f; }
  if (i < BB*MM*WWID) g_mem[i] = 0.f;
  if (i < BB*RR*MM){ g_rw[0][i]=0.f; g_rw[1][i]=0.f; }
  if (i < BB*HH){ g_h0[0][i]=0.f; g_h0[1][i]=0.f; g_c0[i]=0.f;
                  g_h1[0][i]=0.f; g_h1[1][i]=0.f; g_c1[i]=0.f; }
  if (i < BB*MM){ g_prec[0][i]=0.f; g_prec[1][i]=0.f; g_ww[i]=0.f; g_usage[i]=0.f; g_memnorm[i]=0.f; }
}

// ====== warp-GEMV: 4 batches x 4 rows per warp, scalar accumulators ======
#define FMA4S(A,V,W) { A += (V).x*(W).x; A += (V).y*(W).y; A += (V).z*(W).z; A += (V).w*(W).w; }

__device__ __forceinline__ void wgemv16(
    const float* __restrict__ X, int xld, int b0,
    const float* __restrict__ r0, const float* __restrict__ r1,
    const float* __restrict__ r2, const float* __restrict__ r3,
    int K, float acc[16])
{
  const int lane = threadIdx.x & 31;
  const float4* x0 = (const float4*)(X + (size_t)(b0+0)*xld);
  const float4* x1 = (const float4*)(X + (size_t)(b0+1)*xld);
  const float4* x2 = (const float4*)(X + (size_t)(b0+2)*xld);
  const float4* x3 = (const float4*)(X + (size_t)(b0+3)*xld);
  const float4* w0 = (const float4*)r0;
  const float4* w1 = (const float4*)r1;
  const float4* w2 = (const float4*)r2;
  const float4* w3 = (const float4*)r3;
  const int K4 = K >> 2;
  for (int k = lane; k < K4; k += 32){
    float4 a = x0[k], b = x1[k], c = x2[k], d = x3[k];
    float4 wv;
    wv = w0[k]; FMA4S(acc[0],a,wv)  FMA4S(acc[4],b,wv)  FMA4S(acc[8],c,wv)  FMA4S(acc[12],d,wv)
    wv = w1[k]; FMA4S(acc[1],a,wv)  FMA4S(acc[5],b,wv)  FMA4S(acc[9],c,wv)  FMA4S(acc[13],d,wv)
    wv = w2[k]; FMA4S(acc[2],a,wv)  FMA4S(acc[6],b,wv)  FMA4S(acc[10],c,wv) FMA4S(acc[14],d,wv)
    wv = w3[k]; FMA4S(acc[3],a,wv)  FMA4S(acc[7],b,wv)  FMA4S(acc[11],c,wv) FMA4S(acc[15],d,wv)
  }
}
#define ZACC16 float acc[16]; _Pragma("unroll") for (int i_=0;i_<16;i_++) acc[i_]=0.f;
#define RED16  float r[16];   _Pragma("unroll") for (int i_=0;i_<16;i_++) r[i_]=redw(acc[i_]);

// ---------------- pregemm (one-time) ----------------
__global__ void __launch_bounds__(256) k_pregemm(const float* __restrict__ x,
    const float* __restrict__ Wi, const float* __restrict__ bi, const float* __restrict__ bh)
{
  int gw = blockIdx.x*8 + (threadIdx.x>>5);
  int ng = gw >> 9, u = gw & 511;
  int n0 = ng*4;
  ZACC16
  wgemv16(x, DIN, n0,
          Wi + (size_t)(0*HH+u)*DIN, Wi + (size_t)(1*HH+u)*DIN,
          Wi + (size_t)(2*HH+u)*DIN, Wi + (size_t)(3*HH+u)*DIN, DIN, acc);
  RED16
  int lane = threadIdx.x & 31;
  if (lane < 4){
    int n = n0 + lane;
    #pragma unroll
    for (int g=0; g<4; g++)
      g_xg[(size_t)n*(4*HH) + g*HH + u] = r[lane*4+g] + bi[g*HH+u] + bh[g*HH+u];
  }
}

// ---------------- role bodies ----------------
__device__ void lstm0_body(const float* __restrict__ Wh, int t, int rp, int vbid)
{
  int gw = vbid*8 + (threadIdx.x>>5);
  int bg = gw >> 9, u = gw & 511;
  int b0 = bg*4;
  ZACC16
  wgemv16(g_h0[rp], HH, b0,
          Wh + (size_t)(0*HH+u)*HH, Wh + (size_t)(1*HH+u)*HH,
          Wh + (size_t)(2*HH+u)*HH, Wh + (size_t)(3*HH+u)*HH, HH, acc);
  RED16
  int lane = threadIdx.x & 31;
  if (lane < 4){
    int b = b0 + lane;
    const float* xg = g_xg + ((size_t)b*TT + t)*(4*HH);
    float gi = r[lane*4+0] + xg[0*HH+u];
    float gf = r[lane*4+1] + xg[1*HH+u];
    float gg = r[lane*4+2] + xg[1024+u];
    float go = r[lane*4+3] + xg[1536+u];
    int ci = b*HH + u;
    float c2 = sigm(gf)*g_c0[ci] + sigm(gi)*tanhf(gg);
    g_c0[ci] = c2;
    g_h0[1-rp][ci] = sigm(go)*tanhf(c2);
  }
}

__device__ void lstm1_body(const float* __restrict__ Wi, const float* __restrict__ bi,
    const float* __restrict__ Wh, const float* __restrict__ bh, int rp, int vbid)
{
  int gw = vbid*8 + (threadIdx.x>>5);
  int bg = gw >> 9, u = gw & 511;
  int b0 = bg*4;
  ZACC16
  wgemv16(g_h0[1-rp], HH, b0,
          Wi + (size_t)(0*HH+u)*HH, Wi + (size_t)(1*HH+u)*HH,
          Wi + (size_t)(2*HH+u)*HH, Wi + (size_t)(3*HH+u)*HH, HH, acc);
  wgemv16(g_h1[rp], HH, b0,
          Wh + (size_t)(0*HH+u)*HH, Wh + (size_t)(1*HH+u)*HH,
          Wh + (size_t)(2*HH+u)*HH, Wh + (size_t)(3*HH+u)*HH, HH, acc);
  RED16
  int lane = threadIdx.x & 31;
  if (lane < 4){
    int b = b0 + lane;
    float gi = r[lane*4+0] + bi[0*HH+u] + bh[0*HH+u];
    float gf = r[lane*4+1] + bi[1*HH+u] + bh[1*HH+u];
    float gg = r[lane*4+2] + bi[2*HH+u] + bh[2*HH+u];
    float go = r[lane*4+3] + bi[3*HH+u] + bh[3*HH+u];
    int ci = b*HH + u;
    float c2 = sigm(gf)*g_c1[ci] + sigm(gi)*tanhf(gg);
    g_c1[ci] = c2;
    g_h1[1-rp][ci] = sigm(go)*tanhf(c2);
  }
}

__device__ void iface_body(const float* __restrict__ Wif, const float* __restrict__ bif,
    const float* __restrict__ Wmo, const float* __restrict__ bmo, int rp, int vbid)
{
  int gw = vbid*8 + (threadIdx.x>>5);          // 1968 warps = 8 bg x 246 rg
  int bg = gw / 246, rg = gw % 246;
  int b0 = bg*4, rb = rg*4;
  int rr4[4]; const float* rp_[4];
  #pragma unroll
  for (int j=0;j<4;j++){
    int rrow = rb + j; if (rrow > NIF-1) rrow = NIF-1;
    rr4[j] = rrow;
    rp_[j] = (rrow < IFACE) ? (Wif + (size_t)rrow*HH) : (Wmo + (size_t)(rrow-IFACE)*HH);
  }
  ZACC16
  wgemv16(g_h1[1-rp], HH, b0, rp_[0], rp_[1], rp_[2], rp_[3], HH, acc);
  RED16
  int lane = threadIdx.x & 31;
  if (lane < 4){
    int b = b0 + lane;
    #pragma unroll
    for (int j=0;j<4;j++){
      int row = rr4[j];
      float val = r[lane*4+j] + ((row < IFACE) ? bif[row] : bmo[row-IFACE]);
      if (row < IFACE) g_v[b*IFACE + row] = val;
      else             g_outbuf[rp][b*HH + (row-IFACE)] = val;
    }
  }
}

// rv(t-1): reads rw written by rw2(t-1) = g_rw[1-rp_prev].
__device__ void rv_body(int rp_prev, int br)
{
  __shared__ float part[4][64];
  int tt = threadIdx.x, w = tt & 63, mq = tt >> 6;
  int b = br >> 2;
  const float* rwn = g_rw[1-rp_prev] + br*MM;
  const float* mb = g_mem + (size_t)b*MM*WWID;
  float acc = 0.f;
  #pragma unroll 8
  for (int m2 = mq*64; m2 < mq*64+64; m2++) acc += rwn[m2]*mb[(size_t)m2*WWID + w];
  part[mq][w] = acc;
  __syncthreads();
  if (mq == 0) g_rvbuf[br*WWID + w] = part[0][w]+part[1][w]+part[2][w]+part[3][w];
}

__device__ void wrv_body(const float* __restrict__ Wrv, const float* __restrict__ brv,
    int rp_prev, int vbid)
{
  int gw = vbid*8 + (threadIdx.x>>5);   // 1024 warps
  int bg = gw >> 7, rg = gw & 127;
  int b0 = bg*4, rb = rg*4;
  ZACC16
  wgemv16(g_rvbuf, RR*WWID, b0,
          Wrv + (size_t)(rb+0)*(RR*WWID), Wrv + (size_t)(rb+1)*(RR*WWID),
          Wrv + (size_t)(rb+2)*(RR*WWID), Wrv + (size_t)(rb+3)*(RR*WWID),
          RR*WWID, acc);
  RED16
  int lane = threadIdx.x & 31;
  if (lane < 4){
    int b = b0 + lane;
    #pragma unroll
    for (int j=0;j<4;j++){
      int row = rb + j;
      g_out2[b*HH + row] = r[lane*4+j] + brv[row] + g_outbuf[rp_prev][b*HH + row];
    }
  }
}

__device__ void wout_body(const float* __restrict__ Wout, const float* __restrict__ bout,
    float* __restrict__ y, int tprev, int vbid)
{
  int gw = vbid*8 + (threadIdx.x>>5);   // 512 warps
  int bg = gw >> 6, rg = gw & 63;
  int b0 = bg*4, rb = rg*4;
  ZACC16
  wgemv16(g_out2, HH, b0,
          Wout + (size_t)(rb+0)*HH, Wout + (size_t)(rb+1)*HH,
          Wout + (size_t)(rb+2)*HH, Wout + (size_t)(rb+3)*HH, HH, acc);
  RED16
  int lane = threadIdx.x & 31;
  if (lane < 4){
    int b = b0 + lane;
    #pragma unroll
    for (int j=0;j<4;j++){
      int row = rb + j;
      y[((size_t)b*TT + tprev)*DIN + row] = r[lane*4+j] + bout[row];
    }
  }
}

// ---------------- block reductions ----------------
__device__ __forceinline__ float blkmax(float v, volatile float* s8){
  #pragma unroll
  for (int o=16;o;o>>=1) v = fmaxf(v, __shfl_xor_sync(0xffffffffu, v, o));
  if ((threadIdx.x & 31)==0) s8[threadIdx.x>>5] = v;
  __syncthreads();
  float rr = s8[0];
  #pragma unroll
  for (int i=1;i<8;i++) rr = fmaxf(rr, s8[i]);
  __syncthreads();
  return rr;
}
__device__ __forceinline__ float blksum(float v, volatile float* s8){
  #pragma unroll
  for (int o=16;o;o>>=1) v += __shfl_xor_sync(0xffffffffu, v, o);
  if ((threadIdx.x & 31)==0) s8[threadIdx.x>>5] = v;
  __syncthreads();
  float rr = 0.f;
  #pragma unroll
  for (int i=0;i<8;i++) rr += s8[i];
  __syncthreads();
  return rr;
}

// ---- fused memory module ----
__device__ void mem1_body(int rp, int b)
{
  __shared__ float swk[WWID], ser[WWID], swv[WWID], srk[RR*WWID];
  __shared__ float s8[8];
  __shared__ float skey[MM]; __shared__ int sidx[MM];
  __shared__ float sprod[MM], salloc[MM];
  __shared__ float sc[12];
  int m = threadIdx.x;
  const float* vb = g_v + b*IFACE;
  if (m < WWID){ swk[m]=tanhf(vb[WK_OFF+m]); ser[m]=sigm(vb[ER_OFF+m]); swv[m]=tanhf(vb[WV_OFF+m]); }
  srk[m] = tanhf(vb[RK_OFF + m]);
  __syncthreads();
  if (m == 0){
    float s=0.f; for (int w=0;w<WWID;w++) s += swk[w]*swk[w];
    sc[0]=sqrtf(s)+EPSV; sc[1]=softplusf(vb[WS_OFF]);
    sc[10]=sigm(vb[AG_OFF]); sc[11]=sigm(vb[WG_OFF]);
  }
  if (m >= 32 && m < 36){
    int rh = m-32; float s=0.f;
    for (int w=0;w<WWID;w++) s += srk[rh*WWID+w]*srk[rh*WWID+w];
    sc[2+rh]=sqrtf(s)+EPSV; sc[6+rh]=softplusf(vb[RS_OFF+rh]);
  }
  __syncthreads();
  float4 mrow[16];
  float4* mr = (float4*)(g_mem + (size_t)(b*MM+m)*WWID);
  #pragma unroll
  for (int i=0;i<16;i++) mrow[i] = mr[i];
  const float* rwp = g_rw[rp] + b*RR*MM;
  float psi = 1.f;
  #pragma unroll
  for (int rh=0;rh<RR;rh++) psi *= (1.f - sigm(vb[FG_OFF+rh])*rwp[rh*MM+m]);
  float us = g_usage[b*MM+m], wwp = g_ww[b*MM+m];
  us = (us + (1.f-us)*wwp)*psi;
  float dot = 0.f;
  #pragma unroll
  for (int i=0;i<16;i++)
    dot += mrow[i].x*swk[4*i] + mrow[i].y*swk[4*i+1] + mrow[i].z*swk[4*i+2] + mrow[i].w*swk[4*i+3];
  float score = dot/((g_memnorm[b*MM+m]+EPSV)*sc[0]) * sc[1];
  float mx = blkmax(score, s8);
  float e  = expf(score - mx);
  float sm = blksum(e, s8);
  float cww = e/sm;
  float uval = EPSV + (1.f-EPSV)*us;
  skey[m]=uval; sidx[m]=m; __syncthreads();
  for (int k=2;k<=MM;k<<=1){
    for (int j=k>>1;j>0;j>>=1){
      int p = m ^ j;
      if (p > m){
        float ka=skey[m], kb=skey[p]; int ia=sidx[m], ib=sidx[p];
        bool agtb = (ka>kb)||(ka==kb&&ia>ib);
        bool up = ((m & k)==0);
        if (up==agtb){ skey[m]=kb;skey[p]=ka;sidx[m]=ib;sidx[p]=ia; }
      }
      __syncthreads();
    }
  }
  sprod[m]=skey[m]; __syncthreads();
  for (int off=1;off<MM;off<<=1){
    float tv = (m>=off)? sprod[m-off] : 1.f;
    __syncthreads();
    sprod[m] *= tv;
    __syncthreads();
  }
  salloc[sidx[m]] = (1.f - skey[m]) * ((m==0)?1.f:sprod[m-1]);
  __syncthreads();
  float wwv = sc[11]*(sc[10]*salloc[m] + (1.f-sc[10])*cww);
  g_ww[b*MM+m] = wwv;
  g_usage[b*MM+m] = us;
  float wsum = blksum(wwv, s8);
  if (m==0) g_wwsum[b] = wsum;
  float nrm=0.f, d0=0.f, d1=0.f, d2=0.f, d3=0.f;
  #pragma unroll
  for (int i=0;i<16;i++){
    float4 mv = mrow[i];
    int w0 = 4*i;
    mv.x = mv.x*(1.f - wwv*ser[w0  ]) + wwv*swv[w0  ];
    mv.y = mv.y*(1.f - wwv*ser[w0+1]) + wwv*swv[w0+1];
    mv.z = mv.z*(1.f - wwv*ser[w0+2]) + wwv*swv[w0+2];
    mv.w = mv.w*(1.f - wwv*ser[w0+3]) + wwv*swv[w0+3];
    nrm += mv.x*mv.x + mv.y*mv.y + mv.z*mv.z + mv.w*mv.w;
    d0 += mv.x*srk[0*WWID+w0] + mv.y*srk[0*WWID+w0+1] + mv.z*srk[0*WWID+w0+2] + mv.w*srk[0*WWID+w0+3];
    d1 += mv.x*srk[1*WWID+w0] + mv.y*srk[1*WWID+w0+1] + mv.z*srk[1*WWID+w0+2] + mv.w*srk[1*WWID+w0+3];
    d2 += mv.x*srk[2*WWID+w0] + mv.y*srk[2*WWID+w0+1] + mv.z*srk[2*WWID+w0+2] + mv.w*srk[2*WWID+w0+3];
    d3 += mv.x*srk[3*WWID+w0] + mv.y*srk[3*WWID+w0+1] + mv.z*srk[3*WWID+w0+2] + mv.w*srk[3*WWID+w0+3];
    mr[i] = mv;
  }
  float mn = sqrtf(nrm);
  g_memnorm[b*MM+m] = mn;
  float mne = mn + EPSV;
  float dd[4] = {d0,d1,d2,d3};
  #pragma unroll
  for (int rh=0;rh<RR;rh++){
    float sr = dd[rh]/(mne*sc[2+rh]) * sc[6+rh];
    float mx2 = blkmax(sr, s8);
    float e2 = expf(sr - mx2);
    float s2 = blksum(e2, s8);
    g_cwr[(b*RR+rh)*MM+m] = e2/s2;
  }
}

// ---- fused link update + fwd/bwd + read weights + prec ----
__device__ void rw2_body(int rp, int blk)
{
  __shared__ float srw[RR][MM];
  __shared__ float sww[MM], sprec[MM];
  __shared__ float ft[64][65];
  __shared__ float bt[64][64];
  __shared__ float fpart[4][64][RR];
  __shared__ float bpart[4][64][RR];
  int b = blk >> 2, ig = blk & 3;
  int t = threadIdx.x;
  int I0 = ig*64;
  const float* rwp = g_rw[rp] + b*RR*MM;
  #pragma unroll
  for (int rh=0;rh<RR;rh++) srw[rh][t] = rwp[rh*MM+t];
  sww[t] = g_ww[b*MM+t];
  sprec[t] = g_prec[rp][b*MM+t];
  __syncthreads();

  const float* lold = g_link[rp]   + (size_t)b*MM*MM;
  float*       lnew = g_link[1-rp] + (size_t)b*MM*MM;
  int il2 = t & 63, q2 = t >> 6;
  float fa[RR] = {0.f,0.f,0.f,0.f};
  float ba[RR] = {0.f,0.f,0.f,0.f};

  for (int jq = 0; jq < 4; jq++){
    int J0 = jq*64;
    #pragma unroll
    for (int p = 0; p < 16; p++){
      int e = p*256 + t;
      int il = e >> 6, jl = e & 63;
      int i = I0 + il, j = J0 + jl;
      float lo = lold[((size_t)i<<8) + j];
      float ln = (i==j) ? 0.f : (1.f - sww[i] - sww[j])*lo + sww[i]*sprec[j];
      lnew[((size_t)i<<8) + j] = ln;
      ft[il][jl] = ln;
    }
    #pragma unroll
    for (int p = 0; p < 16; p++){
      int e = p*256 + t;
      int jl = e >> 6, il = e & 63;
      int i = I0 + il, j = J0 + jl;
      float lo = lold[((size_t)j<<8) + i];
      float ln = (i==j) ? 0.f : (1.f - sww[j] - sww[i])*lo + sww[j]*sprec[i];
      bt[jl][il] = ln;
    }
    __syncthreads();
    #pragma unroll
    for (int jj = 0; jj < 16; jj++){
      int jl = q2*16 + jj;
      float fv = ft[il2][jl];
      float bv = bt[jl][il2];
      float rw0 = srw[0][J0+jl], rw1 = srw[1][J0+jl], rw2v = srw[2][J0+jl], rw3 = srw[3][J0+jl];
      fa[0] += fv*rw0; fa[1] += fv*rw1; fa[2] += fv*rw2v; fa[3] += fv*rw3;
      ba[0] += bv*rw0; ba[1] += bv*rw1; ba[2] += bv*rw2v; ba[3] += bv*rw3;
    }
    __syncthreads();
  }
  #pragma unroll
  for (int rh=0;rh<RR;rh++){ fpart[q2][il2][rh]=fa[rh]; bpart[q2][il2][rh]=ba[rh]; }
  __syncthreads();
  if (t < 64){
    int i = I0 + t;
    const float* vb = g_v + b*IFACE;
    float* rwn = g_rw[1-rp] + b*RR*MM;
    #pragma unroll
    for (int rh=0;rh<RR;rh++){
      float fr = fpart[0][t][rh]+fpart[1][t][rh]+fpart[2][t][rh]+fpart[3][t][rh];
      float wr = bpart[0][t][rh]+bpart[1][t][rh]+bpart[2][t][rh]+bpart[3][t][rh];
      float x0 = vb[RM_OFF+rh*3], x1 = vb[RM_OFF+rh*3+1], x2 = vb[RM_OFF+rh*3+2];
      float mx = fmaxf(x0, fmaxf(x1, x2));
      float e0 = expf(x0-mx), e1 = expf(x1-mx), e2 = expf(x2-mx);
      float inv = 1.f/(e0+e1+e2);
      rwn[rh*MM+i] = (e0*wr + e1*fr + e2*g_cwr[(b*RR+rh)*MM+i])*inv;
    }
    g_prec[1-rp][b*MM+i] = (1.f - g_wwsum[b])*sprec[i] + sww[i];
  }
}

// ---------------- dispatcher kernels (R12 partition) ----------
// kA(t): lstm1(t) [0,512) + lstm0(t+1) [512,1024) + rv(t-1) [1024,1152)
__global__ void __launch_bounds__(256) kA(const float* __restrict__ Wi, const float* __restrict__ bi,
    const float* __restrict__ Wh, const float* __restrict__ bh,
    const float* __restrict__ Wh0, int rp, int tnext, int en_rv, int en_l0)
{
  if (blockIdx.x < 512)       lstm1_body(Wi, bi, Wh, bh, rp, blockIdx.x);
  else if (blockIdx.x < 1024){ if (en_l0) lstm0_body(Wh0, tnext, 1-rp, blockIdx.x - 512); }
  else if (en_rv)             rv_body(1-rp, blockIdx.x - 1024);
}
// kB(t): iface(t) [0,246) + wrv(t-1) [246,374)
__global__ void __launch_bounds__(256) kB(const float* __restrict__ Wif, const float* __restrict__ bif,
    const float* __restrict__ Wmo, const float* __restrict__ bmo,
    const float* __restrict__ Wrv, const float* __restrict__ brv, int rp, int en)
{
  if (blockIdx.x < 246) iface_body(Wif, bif, Wmo, bmo, rp, blockIdx.x);
  else if (en)          wrv_body(Wrv, brv, 1-rp, blockIdx.x - 246);
}
// kC(t): mem1(t) [0,32) + wout(t-1) [32,96)
__global__ void __launch_bounds__(256) kC(const float* __restrict__ Wout, const float* __restrict__ bout,
    float* __restrict__ y, int rp, int tprev, int en)
{
  if (blockIdx.x < 32) mem1_body(rp, blockIdx.x);
  else if (en)         wout_body(Wout, bout, y, tprev, blockIdx.x - 32);
}
__global__ void __launch_bounds__(256) kD(int rp)
{
  rw2_body(rp, blockIdx.x);
}

// prologue / epilogue standalone kernels
__global__ void __launch_bounds__(256) k_lstm0s(const float* __restrict__ Wh, int t, int rp)
{ lstm0_body(Wh, t, rp, blockIdx.x); }
__global__ void __launch_bounds__(256) k_rvs(int rp_prev)
{ rv_body(rp_prev, blockIdx.x); }
__global__ void __launch_bounds__(256) k_wrvs(const float* __restrict__ Wrv, const float* __restrict__ brv, int rp_prev)
{ wrv_body(Wrv, brv, rp_prev, blockIdx.x); }
__global__ void __launch_bounds__(256) k_wouts(const float* __restrict__ Wout, const float* __restrict__ bout,
    float* __restrict__ y, int tprev)
{ wout_body(Wout, bout, y, tprev, blockIdx.x); }

// ---------------- host: single-stream software pipeline (R12 schedule) ------
extern "C" void kernel_launch(void* const* d_in, const int* in_sizes, int n_in,
                              void* d_out, int out_size)
{
  const float* x     = (const float*)d_in[0];
  const float* Wih0  = (const float*)d_in[1];
  const float* bih0  = (const float*)d_in[2];
  const float* Whh0  = (const float*)d_in[3];
  const float* bhh0  = (const float*)d_in[4];
  const float* Wih1  = (const float*)d_in[5];
  const float* bih1  = (const float*)d_in[6];
  const float* Whh1  = (const float*)d_in[7];
  const float* bhh1  = (const float*)d_in[8];
  const float* Wif   = (const float*)d_in[9];
  const float* bif   = (const float*)d_in[10];
  const float* Wmo   = (const float*)d_in[11];
  const float* bmo   = (const float*)d_in[12];
  const float* Wrv   = (const float*)d_in[13];
  const float* brv   = (const float*)d_in[14];
  const float* Wout  = (const float*)d_in[15];
  const float* bout  = (const float*)d_in[16];
  float* y = (float*)d_out;

  k_init<<<(BB*MM*MM)/256, 256>>>();
  k_pregemm<<<(BB*TT/4)*(HH/8), 256>>>(x, Wih0, bih0, bhh0);
  k_lstm0s<<<512, 256>>>(Whh0, 0, 0);     // prologue: lstm0(0)

  for (int t = 0; t < TT; t++){
    int rp = t & 1;
    kA<<<1152, 256>>>(Wih1, bih1, Whh1, bhh1, Whh0, rp, t+1, t > 0, t < TT-1); // lstm1(t)+lstm0(t+1)+rv(t-1)
    kB<<<374, 256>>>(Wif, bif, Wmo, bmo, Wrv, brv, rp, t > 0);                 // iface(t) + wrv(t-1)
    kC<<<96, 256>>>(Wout, bout, y, rp, t-1, t > 0);                            // mem1(t) + wout(t-1)
    kD<<<128, 256>>>(rp);                                                      // rw2(t)
  }
  // epilogue: tail of t = TT-1  (rp_prev = (TT-1)&1 = 1)
  k_rvs<<<128, 256>>>(1);
  k_wrvs<<<128, 256>>>(Wrv, brv, 1);
  k_wouts<<<64, 256>>>(Wout, bout, y, TT-1);
}

// round 17
// speedup vs baseline: 1.2927x; 1.0068x over previous
#include <cuda_runtime.h>
#include <math.h>

#define BB 32
#define TT 48
#define DIN 256
#define HH 512
#define MM 256
#define WWID 64
#define RR 4
#define IFACE 471
#define NIF 983
#define EPSV 1e-6f

#define RK_OFF 0
#define RS_OFF 256
#define WK_OFF 260
#define WS_OFF 324
#define ER_OFF 325
#define WV_OFF 389
#define FG_OFF 453
#define AG_OFF 457
#define WG_OFF 458
#define RM_OFF 459

// -------- state --------
__device__ float g_h0[2][BB*HH];
__device__ float g_c0[BB*HH];
__device__ float g_h1[2][BB*HH];
__device__ float g_c1[BB*HH];
__device__ float g_mem[BB*MM*WWID];
__device__ float g_link[2][(size_t)BB*MM*MM];
__device__ float g_prec[2][BB*MM];
__device__ float g_rw[2][BB*RR*MM];
__device__ float g_ww[BB*MM];
__device__ float g_usage[BB*MM];
__device__ float g_memnorm[BB*MM];
__device__ float g_v[BB*IFACE];
__device__ float g_cwr[BB*RR*MM];
__device__ float g_wwsum[BB];
__device__ float g_outbuf[2][BB*HH];     // parity double-buffered
__device__ float g_rvbuf[BB*RR*WWID];
__device__ float g_out2[BB*HH];
__device__ float g_xg[(size_t)BB*TT*4*HH];

__device__ __forceinline__ float sigm(float x){ return 1.f/(1.f+expf(-x)); }
__device__ __forceinline__ float softplusf(float x){ return fmaxf(x,0.f) + log1pf(expf(-fabsf(x))); }
__device__ __forceinline__ float redw(float s){
  #pragma unroll
  for (int o=16;o;o>>=1) s += __shfl_xor_sync(0xffffffffu, s, o);
  return s;
}

// ---------------- init ----------------
__global__ void k_init(){
  size_t i = (size_t)blockIdx.x*blockDim.x + threadIdx.x;
  if (i < (size_t)BB*MM*MM){ g_link[0][i]=0.f; g_link[1][i]=0.f; }
  if (i < BB*MM*WWID) g_mem[i] = 0.f;
  if (i < BB*RR*MM){ g_rw[0][i]=0.f; g_rw[1][i]=0.f; }
  if (i < BB*HH){ g_h0[0][i]=0.f; g_h0[1][i]=0.f; g_c0[i]=0.f;
                  g_h1[0][i]=0.f; g_h1[1][i]=0.f; g_c1[i]=0.f; }
  if (i < BB*MM){ g_prec[0][i]=0.f; g_prec[1][i]=0.f; g_ww[i]=0.f; g_usage[i]=0.f; g_memnorm[i]=0.f; }
}

// ====== warp-GEMV: 4 batches x 4 rows per warp, scalar accumulators ======
#define FMA4S(A,V,W) { A += (V).x*(W).x; A += (V).y*(W).y; A += (V).z*(W).z; A += (V).w*(W).w; }

__device__ __forceinline__ void wgemv16(
    const float* __restrict__ X, int xld, int b0,
    const float* __restrict__ r0, const float* __restrict__ r1,
    const float* __restrict__ r2, const float* __restrict__ r3,
    int K, float acc[16])
{
  const int lane = threadIdx.x & 31;
  const float4* x0 = (const float4*)(X + (size_t)(b0+0)*xld);
  const float4* x1 = (const float4*)(X + (size_t)(b0+1)*xld);
  const float4* x2 = (const float4*)(X + (size_t)(b0+2)*xld);
  const float4* x3 = (const float4*)(X + (size_t)(b0+3)*xld);
  const float4* w0 = (const float4*)r0;
  const float4* w1 = (const float4*)r1;
  const float4* w2 = (const float4*)r2;
  const float4* w3 = (const float4*)r3;
  const int K4 = K >> 2;
  for (int k = lane; k < K4; k += 32){
    float4 a = x0[k], b = x1[k], c = x2[k], d = x3[k];
    float4 wv;
    wv = w0[k]; FMA4S(acc[0],a,wv)  FMA4S(acc[4],b,wv)  FMA4S(acc[8],c,wv)  FMA4S(acc[12],d,wv)
    wv = w1[k]; FMA4S(acc[1],a,wv)  FMA4S(acc[5],b,wv)  FMA4S(acc[9],c,wv)  FMA4S(acc[13],d,wv)
    wv = w2[k]; FMA4S(acc[2],a,wv)  FMA4S(acc[6],b,wv)  FMA4S(acc[10],c,wv) FMA4S(acc[14],d,wv)
    wv = w3[k]; FMA4S(acc[3],a,wv)  FMA4S(acc[7],b,wv)  FMA4S(acc[11],c,wv) FMA4S(acc[15],d,wv)
  }
}
#define ZACC16 float acc[16]; _Pragma("unroll") for (int i_=0;i_<16;i_++) acc[i_]=0.f;
#define RED16  float r[16];   _Pragma("unroll") for (int i_=0;i_<16;i_++) r[i_]=redw(acc[i_]);

// ---------------- pregemm (one-time) ----------------
__global__ void __launch_bounds__(256) k_pregemm(const float* __restrict__ x,
    const float* __restrict__ Wi, const float* __restrict__ bi, const float* __restrict__ bh)
{
  int gw = blockIdx.x*8 + (threadIdx.x>>5);
  int ng = gw >> 9, u = gw & 511;
  int n0 = ng*4;
  ZACC16
  wgemv16(x, DIN, n0,
          Wi + (size_t)(0*HH+u)*DIN, Wi + (size_t)(1*HH+u)*DIN,
          Wi + (size_t)(2*HH+u)*DIN, Wi + (size_t)(3*HH+u)*DIN, DIN, acc);
  RED16
  int lane = threadIdx.x & 31;
  if (lane < 4){
    int n = n0 + lane;
    #pragma unroll
    for (int g=0; g<4; g++)
      g_xg[(size_t)n*(4*HH) + g*HH + u] = r[lane*4+g] + bi[g*HH+u] + bh[g*HH+u];
  }
}

// ---------------- role bodies ----------------
__device__ void lstm0_body(const float* __restrict__ Wh, int t, int rp, int vbid)
{
  int gw = vbid*8 + (threadIdx.x>>5);
  int bg = gw >> 9, u = gw & 511;
  int b0 = bg*4;
  ZACC16
  wgemv16(g_h0[rp], HH, b0,
          Wh + (size_t)(0*HH+u)*HH, Wh + (size_t)(1*HH+u)*HH,
          Wh + (size_t)(2*HH+u)*HH, Wh + (size_t)(3*HH+u)*HH, HH, acc);
  RED16
  int lane = threadIdx.x & 31;
  if (lane < 4){
    int b = b0 + lane;
    const float* xg = g_xg + ((size_t)b*TT + t)*(4*HH);
    float gi = r[lane*4+0] + xg[0*HH+u];
    float gf = r[lane*4+1] + xg[1*HH+u];
    float gg = r[lane*4+2] + xg[1024+u];
    float go = r[lane*4+3] + xg[1536+u];
    int ci = b*HH + u;
    float c2 = sigm(gf)*g_c0[ci] + sigm(gi)*tanhf(gg);
    g_c0[ci] = c2;
    g_h0[1-rp][ci] = sigm(go)*tanhf(c2);
  }
}

__device__ void lstm1_body(const float* __restrict__ Wi, const float* __restrict__ bi,
    const float* __restrict__ Wh, const float* __restrict__ bh, int rp, int vbid)
{
  int gw = vbid*8 + (threadIdx.x>>5);
  int bg = gw >> 9, u = gw & 511;
  int b0 = bg*4;
  ZACC16
  wgemv16(g_h0[1-rp], HH, b0,
          Wi + (size_t)(0*HH+u)*HH, Wi + (size_t)(1*HH+u)*HH,
          Wi + (size_t)(2*HH+u)*HH, Wi + (size_t)(3*HH+u)*HH, HH, acc);
  wgemv16(g_h1[rp], HH, b0,
          Wh + (size_t)(0*HH+u)*HH, Wh + (size_t)(1*HH+u)*HH,
          Wh + (size_t)(2*HH+u)*HH, Wh + (size_t)(3*HH+u)*HH, HH, acc);
  RED16
  int lane = threadIdx.x & 31;
  if (lane < 4){
    int b = b0 + lane;
    float gi = r[lane*4+0] + bi[0*HH+u] + bh[0*HH+u];
    float gf = r[lane*4+1] + bi[1*HH+u] + bh[1*HH+u];
    float gg = r[lane*4+2] + bi[2*HH+u] + bh[2*HH+u];
    float go = r[lane*4+3] + bi[3*HH+u] + bh[3*HH+u];
    int ci = b*HH + u;
    float c2 = sigm(gf)*g_c1[ci] + sigm(gi)*tanhf(gg);
    g_c1[ci] = c2;
    g_h1[1-rp][ci] = sigm(go)*tanhf(c2);
  }
}

__device__ void iface_body(const float* __restrict__ Wif, const float* __restrict__ bif,
    const float* __restrict__ Wmo, const float* __restrict__ bmo, int rp, int vbid)
{
  int gw = vbid*8 + (threadIdx.x>>5);          // 1968 warps = 8 bg x 246 rg
  int bg = gw / 246, rg = gw % 246;
  int b0 = bg*4, rb = rg*4;
  int rr4[4]; const float* rp_[4];
  #pragma unroll
  for (int j=0;j<4;j++){
    int rrow = rb + j; if (rrow > NIF-1) rrow = NIF-1;
    rr4[j] = rrow;
    rp_[j] = (rrow < IFACE) ? (Wif + (size_t)rrow*HH) : (Wmo + (size_t)(rrow-IFACE)*HH);
  }
  ZACC16
  wgemv16(g_h1[1-rp], HH, b0, rp_[0], rp_[1], rp_[2], rp_[3], HH, acc);
  RED16
  int lane = threadIdx.x & 31;
  if (lane < 4){
    int b = b0 + lane;
    #pragma unroll
    for (int j=0;j<4;j++){
      int row = rr4[j];
      float val = r[lane*4+j] + ((row < IFACE) ? bif[row] : bmo[row-IFACE]);
      if (row < IFACE) g_v[b*IFACE + row] = val;
      else             g_outbuf[rp][b*HH + (row-IFACE)] = val;
    }
  }
}

// rv(t-1): reads rw written by rw2(t-1) = g_rw[1-rp_prev].
__device__ void rv_body(int rp_prev, int br)
{
  __shared__ float part[4][64];
  int tt = threadIdx.x, w = tt & 63, mq = tt >> 6;
  int b = br >> 2;
  const float* rwn = g_rw[1-rp_prev] + br*MM;
  const float* mb = g_mem + (size_t)b*MM*WWID;
  float acc = 0.f;
  #pragma unroll 8
  for (int m2 = mq*64; m2 < mq*64+64; m2++) acc += rwn[m2]*mb[(size_t)m2*WWID + w];
  part[mq][w] = acc;
  __syncthreads();
  if (mq == 0) g_rvbuf[br*WWID + w] = part[0][w]+part[1][w]+part[2][w]+part[3][w];
}

__device__ void wrv_body(const float* __restrict__ Wrv, const float* __restrict__ brv,
    int rp_prev, int vbid)
{
  int gw = vbid*8 + (threadIdx.x>>5);   // 1024 warps
  int bg = gw >> 7, rg = gw & 127;
  int b0 = bg*4, rb = rg*4;
  ZACC16
  wgemv16(g_rvbuf, RR*WWID, b0,
          Wrv + (size_t)(rb+0)*(RR*WWID), Wrv + (size_t)(rb+1)*(RR*WWID),
          Wrv + (size_t)(rb+2)*(RR*WWID), Wrv + (size_t)(rb+3)*(RR*WWID),
          RR*WWID, acc);
  RED16
  int lane = threadIdx.x & 31;
  if (lane < 4){
    int b = b0 + lane;
    #pragma unroll
    for (int j=0;j<4;j++){
      int row = rb + j;
      g_out2[b*HH + row] = r[lane*4+j] + brv[row] + g_outbuf[rp_prev][b*HH + row];
    }
  }
}

__device__ void wout_body(const float* __restrict__ Wout, const float* __restrict__ bout,
    float* __restrict__ y, int tprev, int vbid)
{
  int gw = vbid*8 + (threadIdx.x>>5);   // 512 warps
  int bg = gw >> 6, rg = gw & 63;
  int b0 = bg*4, rb = rg*4;
  ZACC16
  wgemv16(g_out2, HH, b0,
          Wout + (size_t)(rb+0)*HH, Wout + (size_t)(rb+1)*HH,
          Wout + (size_t)(rb+2)*HH, Wout + (size_t)(rb+3)*HH, HH, acc);
  RED16
  int lane = threadIdx.x & 31;
  if (lane < 4){
    int b = b0 + lane;
    #pragma unroll
    for (int j=0;j<4;j++){
      int row = rb + j;
      y[((size_t)b*TT + tprev)*DIN + row] = r[lane*4+j] + bout[row];
    }
  }
}

// ---------------- block reductions ----------------
__device__ __forceinline__ float blkmax(float v, volatile float* s8){
  #pragma unroll
  for (int o=16;o;o>>=1) v = fmaxf(v, __shfl_xor_sync(0xffffffffu, v, o));
  if ((threadIdx.x & 31)==0) s8[threadIdx.x>>5] = v;
  __syncthreads();
  float rr = s8[0];
  #pragma unroll
  for (int i=1;i<8;i++) rr = fmaxf(rr, s8[i]);
  __syncthreads();
  return rr;
}
__device__ __forceinline__ float blksum(float v, volatile float* s8){
  #pragma unroll
  for (int o=16;o;o>>=1) v += __shfl_xor_sync(0xffffffffu, v, o);
  if ((threadIdx.x & 31)==0) s8[threadIdx.x>>5] = v;
  __syncthreads();
  float rr = 0.f;
  #pragma unroll
  for (int i=0;i<8;i++) rr += s8[i];
  __syncthreads();
  return rr;
}

// ---- fused memory module ----
__device__ void mem1_body(int rp, int b)
{
  __shared__ float swk[WWID], ser[WWID], swv[WWID], srk[RR*WWID];
  __shared__ float s8[8];
  __shared__ float skey[MM]; __shared__ int sidx[MM];
  __shared__ float sprod[MM], salloc[MM];
  __shared__ float sc[12];
  int m = threadIdx.x;
  const float* vb = g_v + b*IFACE;
  if (m < WWID){ swk[m]=tanhf(vb[WK_OFF+m]); ser[m]=sigm(vb[ER_OFF+m]); swv[m]=tanhf(vb[WV_OFF+m]); }
  srk[m] = tanhf(vb[RK_OFF + m]);
  __syncthreads();
  if (m == 0){
    float s=0.f; for (int w=0;w<WWID;w++) s += swk[w]*swk[w];
    sc[0]=sqrtf(s)+EPSV; sc[1]=softplusf(vb[WS_OFF]);
    sc[10]=sigm(vb[AG_OFF]); sc[11]=sigm(vb[WG_OFF]);
  }
  if (m >= 32 && m < 36){
    int rh = m-32; float s=0.f;
    for (int w=0;w<WWID;w++) s += srk[rh*WWID+w]*srk[rh*WWID+w];
    sc[2+rh]=sqrtf(s)+EPSV; sc[6+rh]=softplusf(vb[RS_OFF+rh]);
  }
  __syncthreads();
  float4 mrow[16];
  float4* mr = (float4*)(g_mem + (size_t)(b*MM+m)*WWID);
  #pragma unroll
  for (int i=0;i<16;i++) mrow[i] = mr[i];
  const float* rwp = g_rw[rp] + b*RR*MM;
  float psi = 1.f;
  #pragma unroll
  for (int rh=0;rh<RR;rh++) psi *= (1.f - sigm(vb[FG_OFF+rh])*rwp[rh*MM+m]);
  float us = g_usage[b*MM+m], wwp = g_ww[b*MM+m];
  us = (us + (1.f-us)*wwp)*psi;
  float dot = 0.f;
  #pragma unroll
  for (int i=0;i<16;i++)
    dot += mrow[i].x*swk[4*i] + mrow[i].y*swk[4*i+1] + mrow[i].z*swk[4*i+2] + mrow[i].w*swk[4*i+3];
  float score = dot/((g_memnorm[b*MM+m]+EPSV)*sc[0]) * sc[1];
  float mx = blkmax(score, s8);
  float e  = expf(score - mx);
  float sm = blksum(e, s8);
  float cww = e/sm;
  float uval = EPSV + (1.f-EPSV)*us;
  skey[m]=uval; sidx[m]=m; __syncthreads();
  for (int k=2;k<=MM;k<<=1){
    for (int j=k>>1;j>0;j>>=1){
      int p = m ^ j;
      if (p > m){
        float ka=skey[m], kb=skey[p]; int ia=sidx[m], ib=sidx[p];
        bool agtb = (ka>kb)||(ka==kb&&ia>ib);
        bool up = ((m & k)==0);
        if (up==agtb){ skey[m]=kb;skey[p]=ka;sidx[m]=ib;sidx[p]=ia; }
      }
      __syncthreads();
    }
  }
  sprod[m]=skey[m]; __syncthreads();
  for (int off=1;off<MM;off<<=1){
    float tv = (m>=off)? sprod[m-off] : 1.f;
    __syncthreads();
    sprod[m] *= tv;
    __syncthreads();
  }
  salloc[sidx[m]] = (1.f - skey[m]) * ((m==0)?1.f:sprod[m-1]);
  __syncthreads();
  float wwv = sc[11]*(sc[10]*salloc[m] + (1.f-sc[10])*cww);
  g_ww[b*MM+m] = wwv;
  g_usage[b*MM+m] = us;
  float wsum = blksum(wwv, s8);
  if (m==0) g_wwsum[b] = wsum;
  float nrm=0.f, d0=0.f, d1=0.f, d2=0.f, d3=0.f;
  #pragma unroll
  for (int i=0;i<16;i++){
    float4 mv = mrow[i];
    int w0 = 4*i;
    mv.x = mv.x*(1.f - wwv*ser[w0  ]) + wwv*swv[w0  ];
    mv.y = mv.y*(1.f - wwv*ser[w0+1]) + wwv*swv[w0+1];
    mv.z = mv.z*(1.f - wwv*ser[w0+2]) + wwv*swv[w0+2];
    mv.w = mv.w*(1.f - wwv*ser[w0+3]) + wwv*swv[w0+3];
    nrm += mv.x*mv.x + mv.y*mv.y + mv.z*mv.z + mv.w*mv.w;
    d0 += mv.x*srk[0*WWID+w0] + mv.y*srk[0*WWID+w0+1] + mv.z*srk[0*WWID+w0+2] + mv.w*srk[0*WWID+w0+3];
    d1 += mv.x*srk[1*WWID+w0] + mv.y*srk[1*WWID+w0+1] + mv.z*srk[1*WWID+w0+2] + mv.w*srk[1*WWID+w0+3];
    d2 += mv.x*srk[2*WWID+w0] + mv.y*srk[2*WWID+w0+1] + mv.z*srk[2*WWID+w0+2] + mv.w*srk[2*WWID+w0+3];
    d3 += mv.x*srk[3*WWID+w0] + mv.y*srk[3*WWID+w0+1] + mv.z*srk[3*WWID+w0+2] + mv.w*srk[3*WWID+w0+3];
    mr[i] = mv;
  }
  float mn = sqrtf(nrm);
  g_memnorm[b*MM+m] = mn;
  float mne = mn + EPSV;
  float dd[4] = {d0,d1,d2,d3};
  #pragma unroll
  for (int rh=0;rh<RR;rh++){
    float sr = dd[rh]/(mne*sc[2+rh]) * sc[6+rh];
    float mx2 = blkmax(sr, s8);
    float e2 = expf(sr - mx2);
    float s2 = blksum(e2, s8);
    g_cwr[(b*RR+rh)*MM+m] = e2/s2;
  }
}

// ---- fused link update + fwd/bwd + read weights + prec ----
__device__ void rw2_body(int rp, int blk)
{
  __shared__ float srw[RR][MM];
  __shared__ float sww[MM], sprec[MM];
  __shared__ float ft[64][65];
  __shared__ float bt[64][64];
  __shared__ float fpart[4][64][RR];
  __shared__ float bpart[4][64][RR];
  int b = blk >> 2, ig = blk & 3;
  int t = threadIdx.x;
  int I0 = ig*64;
  const float* rwp = g_rw[rp] + b*RR*MM;
  #pragma unroll
  for (int rh=0;rh<RR;rh++) srw[rh][t] = rwp[rh*MM+t];
  sww[t] = g_ww[b*MM+t];
  sprec[t] = g_prec[rp][b*MM+t];
  __syncthreads();

  const float* lold = g_link[rp]   + (size_t)b*MM*MM;
  float*       lnew = g_link[1-rp] + (size_t)b*MM*MM;
  int il2 = t & 63, q2 = t >> 6;
  float fa[RR] = {0.f,0.f,0.f,0.f};
  float ba[RR] = {0.f,0.f,0.f,0.f};

  for (int jq = 0; jq < 4; jq++){
    int J0 = jq*64;
    #pragma unroll
    for (int p = 0; p < 16; p++){
      int e = p*256 + t;
      int il = e >> 6, jl = e & 63;
      int i = I0 + il, j = J0 + jl;
      float lo = lold[((size_t)i<<8) + j];
      float ln = (i==j) ? 0.f : (1.f - sww[i] - sww[j])*lo + sww[i]*sprec[j];
      lnew[((size_t)i<<8) + j] = ln;
      ft[il][jl] = ln;
    }
    #pragma unroll
    for (int p = 0; p < 16; p++){
      int e = p*256 + t;
      int jl = e >> 6, il = e & 63;
      int i = I0 + il, j = J0 + jl;
      float lo = lold[((size_t)j<<8) + i];
      float ln = (i==j) ? 0.f : (1.f - sww[j] - sww[i])*lo + sww[j]*sprec[i];
      bt[jl][il] = ln;
    }
    __syncthreads();
    #pragma unroll
    for (int jj = 0; jj < 16; jj++){
      int jl = q2*16 + jj;
      float fv = ft[il2][jl];
      float bv = bt[jl][il2];
      float rw0 = srw[0][J0+jl], rw1 = srw[1][J0+jl], rw2v = srw[2][J0+jl], rw3 = srw[3][J0+jl];
      fa[0] += fv*rw0; fa[1] += fv*rw1; fa[2] += fv*rw2v; fa[3] += fv*rw3;
      ba[0] += bv*rw0; ba[1] += bv*rw1; ba[2] += bv*rw2v; ba[3] += bv*rw3;
    }
    __syncthreads();
  }
  #pragma unroll
  for (int rh=0;rh<RR;rh++){ fpart[q2][il2][rh]=fa[rh]; bpart[q2][il2][rh]=ba[rh]; }
  __syncthreads();
  if (t < 64){
    int i = I0 + t;
    const float* vb = g_v + b*IFACE;
    float* rwn = g_rw[1-rp] + b*RR*MM;
    #pragma unroll
    for (int rh=0;rh<RR;rh++){
      float fr = fpart[0][t][rh]+fpart[1][t][rh]+fpart[2][t][rh]+fpart[3][t][rh];
      float wr = bpart[0][t][rh]+bpart[1][t][rh]+bpart[2][t][rh]+bpart[3][t][rh];
      float x0 = vb[RM_OFF+rh*3], x1 = vb[RM_OFF+rh*3+1], x2 = vb[RM_OFF+rh*3+2];
      float mx = fmaxf(x0, fmaxf(x1, x2));
      float e0 = expf(x0-mx), e1 = expf(x1-mx), e2 = expf(x2-mx);
      float inv = 1.f/(e0+e1+e2);
      rwn[rh*MM+i] = (e0*wr + e1*fr + e2*g_cwr[(b*RR+rh)*MM+i])*inv;
    }
    g_prec[1-rp][b*MM+i] = (1.f - g_wwsum[b])*sprec[i] + sww[i];
  }
}

// ---------------- dispatcher kernels (R12 partition) ----------
// kA(t): lstm1(t) [0,512) + lstm0(t+1) [512,1024) + rv(t-1) [1024,1152)
__global__ void __launch_bounds__(256) kA(const float* __restrict__ Wi, const float* __restrict__ bi,
    const float* __restrict__ Wh, const float* __restrict__ bh,
    const float* __restrict__ Wh0, int rp, int tnext, int en_rv, int en_l0)
{
  if (blockIdx.x < 512)       lstm1_body(Wi, bi, Wh, bh, rp, blockIdx.x);
  else if (blockIdx.x < 1024){ if (en_l0) lstm0_body(Wh0, tnext, 1-rp, blockIdx.x - 512); }
  else if (en_rv)             rv_body(1-rp, blockIdx.x - 1024);
}
// kB(t): iface(t) [0,246) + wrv(t-1) [246,374)
__global__ void __launch_bounds__(256) kB(const float* __restrict__ Wif, const float* __restrict__ bif,
    const float* __restrict__ Wmo, const float* __restrict__ bmo,
    const float* __restrict__ Wrv, const float* __restrict__ brv, int rp, int en)
{
  if (blockIdx.x < 246) iface_body(Wif, bif, Wmo, bmo, rp, blockIdx.x);
  else if (en)          wrv_body(Wrv, brv, 1-rp, blockIdx.x - 246);
}
// kC(t): mem1(t) [0,32) + wout(t-1) [32,96)
__global__ void __launch_bounds__(256) kC(const float* __restrict__ Wout, const float* __restrict__ bout,
    float* __restrict__ y, int rp, int tprev, int en)
{
  if (blockIdx.x < 32) mem1_body(rp, blockIdx.x);
  else if (en)         wout_body(Wout, bout, y, tprev, blockIdx.x - 32);
}
__global__ void __launch_bounds__(256) kD(int rp)
{
  rw2_body(rp, blockIdx.x);
}

// prologue / epilogue standalone kernels
__global__ void __launch_bounds__(256) k_lstm0s(const float* __restrict__ Wh, int t, int rp)
{ lstm0_body(Wh, t, rp, blockIdx.x); }
__global__ void __launch_bounds__(256) k_rvs(int rp_prev)
{ rv_body(rp_prev, blockIdx.x); }
__global__ void __launch_bounds__(256) k_wrvs(const float* __restrict__ Wrv, const float* __restrict__ brv, int rp_prev)
{ wrv_body(Wrv, brv, rp_prev, blockIdx.x); }
__global__ void __launch_bounds__(256) k_wouts(const float* __restrict__ Wout, const float* __restrict__ bout,
    float* __restrict__ y, int tprev)
{ wout_body(Wout, bout, y, tprev, blockIdx.x); }

// ---------------- host: single-stream software pipeline (R12 schedule) ------
extern "C" void kernel_launch(void* const* d_in, const int* in_sizes, int n_in,
                              void* d_out, int out_size)
{
  const float* x     = (const float*)d_in[0];
  const float* Wih0  = (const float*)d_in[1];
  const float* bih0  = (const float*)d_in[2];
  const float* Whh0  = (const float*)d_in[3];
  const float* bhh0  = (const float*)d_in[4];
  const float* Wih1  = (const float*)d_in[5];
  const float* bih1  = (const float*)d_in[6];
  const float* Whh1  = (const float*)d_in[7];
  const float* bhh1  = (const float*)d_in[8];
  const float* Wif   = (const float*)d_in[9];
  const float* bif   = (const float*)d_in[10];
  const float* Wmo   = (const float*)d_in[11];
  const float* bmo   = (const float*)d_in[12];
  const float* Wrv   = (const float*)d_in[13];
  const float* brv   = (const float*)d_in[14];
  const float* Wout  = (const float*)d_in[15];
  const float* bout  = (const float*)d_in[16];
  float* y = (float*)d_out;

  k_init<<<(BB*MM*MM)/256, 256>>>();
  k_pregemm<<<(BB*TT/4)*(HH/8), 256>>>(x, Wih0, bih0, bhh0);
  k_lstm0s<<<512, 256>>>(Whh0, 0, 0);     // prologue: lstm0(0)

  for (int t = 0; t < TT; t++){
    int rp = t & 1;
    kA<<<1152, 256>>>(Wih1, bih1, Whh1, bhh1, Whh0, rp, t+1, t > 0, t < TT-1); // lstm1(t)+lstm0(t+1)+rv(t-1)
    kB<<<374, 256>>>(Wif, bif, Wmo, bmo, Wrv, brv, rp, t > 0);                 // iface(t) + wrv(t-1)
    kC<<<96, 256>>>(Wout, bout, y, rp, t-1, t > 0);                            // mem1(t) + wout(t-1)
    kD<<<128, 256>>>(rp);                                                      // rw2(t)
  }
  // epilogue: tail of t = TT-1  (rp_prev = (TT-1)&1 = 1)
  k_rvs<<<128, 256>>>(1);
  k_wrvs<<<128, 256>>>(Wrv, brv, 1);
  k_wouts<<<64, 256>>>(Wout, bout, y, TT-1);
}